// round 1
// baseline (speedup 1.0000x reference)
#include <cuda_runtime.h>
#include <cuda_bf16.h>
#include <math.h>

// Problem constants
#define N_NODES   10000
#define N_EDGES   160000
#define IN_FEATS  512
#define HEADS     8
#define OUT_FEATS 64
#define HF        (HEADS * OUT_FEATS)   // 512
#define NEG_SLOPE 0.2f

// ---------------- scratch (device globals; no allocs allowed) ----------------
__device__ float g_h[N_NODES * HF];          // projected features [N, 512]
__device__ float g_el[N_NODES * HEADS];
__device__ float g_er[N_NODES * HEADS];
__device__ int   g_cnt[N_NODES + 1];
__device__ int   g_off[N_NODES + 1];
__device__ int   g_cur[N_NODES];
__device__ int   g_perm[N_EDGES];

// ---------------- GEMM: h = feat @ W  (M=10000, N=512, K=512) ----------------
#define BM 128
#define BN 64
#define BK 16
#define TM 8
#define TN 4

__global__ __launch_bounds__(256) void sgemm_kernel(
    const float* __restrict__ A,   // [M, 512]
    const float* __restrict__ B,   // [512, 512]
    float* __restrict__ C,         // [M, 512]
    int M)
{
    __shared__ float As[BK][BM];
    __shared__ float Bs[BK][BN];

    const int K = 512, N = 512;
    int tid = threadIdx.x;
    int bm = blockIdx.y * BM;
    int bn = blockIdx.x * BN;

    float acc[TM][TN];
    #pragma unroll
    for (int i = 0; i < TM; i++)
        #pragma unroll
        for (int j = 0; j < TN; j++) acc[i][j] = 0.0f;

    int ty = tid >> 4;    // 0..15, M direction
    int tx = tid & 15;    // 0..15, N direction

    for (int k0 = 0; k0 < K; k0 += BK) {
        // Load A tile: 128 rows x 16 k, 2 float4 per thread
        #pragma unroll
        for (int p = 0; p < 2; p++) {
            int r = (tid >> 2) + p * 64;   // 0..127
            int c = (tid & 3) * 4;         // 0,4,8,12
            int grow = bm + r;
            float4 v = make_float4(0.f, 0.f, 0.f, 0.f);
            if (grow < M)
                v = *(const float4*)(A + (size_t)grow * K + k0 + c);
            As[c + 0][r] = v.x;
            As[c + 1][r] = v.y;
            As[c + 2][r] = v.z;
            As[c + 3][r] = v.w;
        }
        // Load B tile: 16 k x 64 n, 1 float4 per thread
        {
            int r = tid >> 4;              // 0..15
            int c = (tid & 15) * 4;        // 0..60
            float4 v = *(const float4*)(B + (size_t)(k0 + r) * N + bn + c);
            *(float4*)&Bs[r][c] = v;
        }
        __syncthreads();

        #pragma unroll
        for (int kk = 0; kk < BK; kk++) {
            float a[TM], b[TN];
            #pragma unroll
            for (int i = 0; i < TM; i++) a[i] = As[kk][ty * TM + i];
            #pragma unroll
            for (int j = 0; j < TN; j++) b[j] = Bs[kk][tx * TN + j];
            #pragma unroll
            for (int i = 0; i < TM; i++)
                #pragma unroll
                for (int j = 0; j < TN; j++)
                    acc[i][j] = fmaf(a[i], b[j], acc[i][j]);
        }
        __syncthreads();
    }

    #pragma unroll
    for (int i = 0; i < TM; i++) {
        int grow = bm + ty * TM + i;
        if (grow < M) {
            float4 v = make_float4(acc[i][0], acc[i][1], acc[i][2], acc[i][3]);
            *(float4*)(C + (size_t)grow * N + bn + tx * TN) = v;
        }
    }
}

// -------------- el/er: per-(node,head) dot with attn_l / attn_r --------------
__global__ __launch_bounds__(256) void attn_dots_kernel(
    const float* __restrict__ h,
    const float* __restrict__ al,   // [8,64]
    const float* __restrict__ ar,   // [8,64]
    float* __restrict__ el,
    float* __restrict__ er)
{
    int n = blockIdx.x;
    int hd = threadIdx.x >> 5;
    int lane = threadIdx.x & 31;

    const float* hp = h + (size_t)n * HF + hd * OUT_FEATS;
    float x0 = hp[lane];
    float x1 = hp[lane + 32];
    float l = x0 * al[hd * OUT_FEATS + lane] + x1 * al[hd * OUT_FEATS + lane + 32];
    float r = x0 * ar[hd * OUT_FEATS + lane] + x1 * ar[hd * OUT_FEATS + lane + 32];
    #pragma unroll
    for (int o = 16; o > 0; o >>= 1) {
        l += __shfl_xor_sync(0xFFFFFFFFu, l, o);
        r += __shfl_xor_sync(0xFFFFFFFFu, r, o);
    }
    if (lane == 0) {
        el[n * HEADS + hd] = l;
        er[n * HEADS + hd] = r;
    }
}

// ------------------------------ CSR building ---------------------------------
__global__ void zero_counts_kernel()
{
    int i = blockIdx.x * blockDim.x + threadIdx.x;
    if (i <= N_NODES) g_cnt[i] = 0;
    if (i < N_NODES)  g_cur[i] = 0;
}

__global__ void count_kernel(const int* __restrict__ dst)
{
    int e = blockIdx.x * blockDim.x + threadIdx.x;
    if (e < N_EDGES) atomicAdd(&g_cnt[dst[e]], 1);
}

#define SCAN_CHUNK 10
__global__ __launch_bounds__(1024) void scan_kernel()
{
    __shared__ int sh[1024];
    int t = threadIdx.x;
    int base = t * SCAN_CHUNK;
    int vloc[SCAN_CHUNK];
    int s = 0;
    #pragma unroll
    for (int j = 0; j < SCAN_CHUNK; j++) {
        int idx = base + j;
        int c = (idx < N_NODES) ? g_cnt[idx] : 0;
        vloc[j] = c;
        s += c;
    }
    sh[t] = s;
    __syncthreads();
    for (int d = 1; d < 1024; d <<= 1) {
        int add = (t >= d) ? sh[t - d] : 0;
        __syncthreads();
        sh[t] += add;
        __syncthreads();
    }
    int run = sh[t] - s;   // exclusive prefix of this thread's chunk
    #pragma unroll
    for (int j = 0; j < SCAN_CHUNK; j++) {
        int idx = base + j;
        if (idx <= N_NODES) g_off[idx] = run;
        run += vloc[j];
    }
}

__global__ void fill_kernel(const int* __restrict__ dst)
{
    int e = blockIdx.x * blockDim.x + threadIdx.x;
    if (e < N_EDGES) {
        int d = dst[e];
        int pos = atomicAdd(&g_cur[d], 1);
        g_perm[g_off[d] + pos] = e;
    }
}

// ---------- softmax over incoming edges + weighted aggregation ---------------
// One block per dst node; one warp per head.
__global__ __launch_bounds__(256) void aggregate_kernel(
    const int* __restrict__ src,
    const float* __restrict__ bias,
    float* __restrict__ out)
{
    int n = blockIdx.x;
    int hd = threadIdx.x >> 5;
    int lane = threadIdx.x & 31;

    int beg = g_off[n];
    int end = g_off[n + 1];
    float er_nh = g_er[n * HEADS + hd];

    // Pass 1: max
    float m = -INFINITY;
    for (int i = beg + lane; i < end; i += 32) {
        int e = g_perm[i];
        int s = src[e];
        float v = g_el[s * HEADS + hd] + er_nh;
        v = (v > 0.f) ? v : NEG_SLOPE * v;
        m = fmaxf(m, v);
    }
    #pragma unroll
    for (int o = 16; o > 0; o >>= 1)
        m = fmaxf(m, __shfl_xor_sync(0xFFFFFFFFu, m, o));

    // Pass 2: sum of exp
    float ssum = 0.f;
    for (int i = beg + lane; i < end; i += 32) {
        int e = g_perm[i];
        int s = src[e];
        float v = g_el[s * HEADS + hd] + er_nh;
        v = (v > 0.f) ? v : NEG_SLOPE * v;
        ssum += __expf(v - m);
    }
    #pragma unroll
    for (int o = 16; o > 0; o >>= 1)
        ssum += __shfl_xor_sync(0xFFFFFFFFu, ssum, o);

    float inv = (ssum > 0.f) ? (1.0f / ssum) : 0.f;

    // Pass 3: weighted aggregation (warp processes each edge together)
    float acc0 = 0.f, acc1 = 0.f;
    for (int i = beg; i < end; ++i) {
        int e = g_perm[i];
        int s = src[e];
        float v = g_el[s * HEADS + hd] + er_nh;
        v = (v > 0.f) ? v : NEG_SLOPE * v;
        float a = __expf(v - m) * inv;
        const float* hp = g_h + (size_t)s * HF + hd * OUT_FEATS;
        acc0 = fmaf(a, hp[lane], acc0);
        acc1 = fmaf(a, hp[lane + 32], acc1);
    }

    int ob = n * HF + hd * OUT_FEATS;
    out[ob + lane]      = acc0 + bias[hd * OUT_FEATS + lane];
    out[ob + lane + 32] = acc1 + bias[hd * OUT_FEATS + lane + 32];
}

// ------------------------------- launcher ------------------------------------
extern "C" void kernel_launch(void* const* d_in, const int* in_sizes, int n_in,
                              void* d_out, int out_size)
{
    const float* feat   = (const float*)d_in[0];  // [10000, 512]
    const float* W      = (const float*)d_in[1];  // [512, 512]
    const float* attn_l = (const float*)d_in[2];  // [8, 64]
    const float* attn_r = (const float*)d_in[3];  // [8, 64]
    const float* bias   = (const float*)d_in[4];  // [512]
    const int*   src    = (const int*)d_in[5];    // [160000]
    const int*   dst    = (const int*)d_in[6];    // [160000]
    float* out = (float*)d_out;                   // [10000, 8, 64]

    float* d_h;
    cudaGetSymbolAddress((void**)&d_h, g_h);
    float* d_el; cudaGetSymbolAddress((void**)&d_el, g_el);
    float* d_er; cudaGetSymbolAddress((void**)&d_er, g_er);

    // 1) projection GEMM
    {
        dim3 grid(HF / BN, (N_NODES + BM - 1) / BM);
        sgemm_kernel<<<grid, 256>>>(feat, W, d_h, N_NODES);
    }
    // 2) attention dot products
    attn_dots_kernel<<<N_NODES, 256>>>(d_h, attn_l, attn_r, d_el, d_er);
    // 3) CSR build
    zero_counts_kernel<<<(N_NODES + 256) / 256, 256>>>();
    count_kernel<<<(N_EDGES + 255) / 256, 256>>>(dst);
    scan_kernel<<<1, 1024>>>();
    fill_kernel<<<(N_EDGES + 255) / 256, 256>>>(dst);
    // 4) softmax + aggregation
    aggregate_kernel<<<N_NODES, 256>>>(src, bias, out);
}

// round 3
// speedup vs baseline: 1.4033x; 1.4033x over previous
#include <cuda_runtime.h>
#include <cuda_bf16.h>
#include <math.h>
#include <stdint.h>

// Problem constants
#define N_NODES   10000
#define N_EDGES   160000
#define IN_FEATS  512
#define HEADS     8
#define OUT_FEATS 64
#define HF        (HEADS * OUT_FEATS)   // 512
#define NEG_SLOPE 0.2f

// ---------------- scratch (device globals; no allocs allowed) ----------------
__device__ float g_h[N_NODES * HF];          // projected features [N, 512]
__device__ float g_el[N_NODES * HEADS];
__device__ float g_er[N_NODES * HEADS];
__device__ int   g_cnt[N_NODES + 1];
__device__ int   g_off[N_NODES + 1];
__device__ int   g_cur[N_NODES];
__device__ int   g_perm[N_EDGES];
__device__ __nv_bfloat16 g_Wh[HF * IN_FEATS];      // W^T hi: [n][k]
__device__ __nv_bfloat16 g_Wl[HF * IN_FEATS];      // W^T lo: [n][k]
__device__ __nv_bfloat16 g_Ah[N_NODES * IN_FEATS]; // feat hi: [m][k]
__device__ __nv_bfloat16 g_Al[N_NODES * IN_FEATS]; // feat lo: [m][k]

// ------------------------------ PTX helpers ----------------------------------
__device__ __forceinline__ uint32_t smem_u32(const void* p) {
    uint32_t a;
    asm("{ .reg .u64 t; cvta.to.shared.u64 t, %1; cvt.u32.u64 %0, t; }"
        : "=r"(a) : "l"(p));
    return a;
}
__device__ __forceinline__ void cp_async16(uint32_t sa, const void* gp, int sz) {
    asm volatile("cp.async.cg.shared.global [%0], [%1], 16, %2;"
                 :: "r"(sa), "l"(gp), "r"(sz));
}
__device__ __forceinline__ void cp_commit() {
    asm volatile("cp.async.commit_group;" ::: "memory");
}
template <int N>
__device__ __forceinline__ void cp_wait() {
    asm volatile("cp.async.wait_group %0;" :: "n"(N) : "memory");
}
__device__ __forceinline__ void ldsm4(uint32_t* r, uint32_t addr) {
    asm volatile("ldmatrix.sync.aligned.m8n8.x4.shared.b16 {%0,%1,%2,%3}, [%4];"
                 : "=r"(r[0]), "=r"(r[1]), "=r"(r[2]), "=r"(r[3]) : "r"(addr));
}
__device__ __forceinline__ void mma16816(float* d, const uint32_t* a, const uint32_t* b) {
    asm volatile(
        "mma.sync.aligned.m16n8k16.row.col.f32.bf16.bf16.f32 "
        "{%0,%1,%2,%3}, {%4,%5,%6,%7}, {%8,%9}, {%0,%1,%2,%3};"
        : "+f"(d[0]), "+f"(d[1]), "+f"(d[2]), "+f"(d[3])
        : "r"(a[0]), "r"(a[1]), "r"(a[2]), "r"(a[3]), "r"(b[0]), "r"(b[1]));
}

// ====================== pre-passes: hi/lo bf16 splits =========================
__global__ __launch_bounds__(256) void wsplit_kernel(const float* __restrict__ W)
{
    __shared__ float tile[32][33];
    int bx = blockIdx.x;  // n tile
    int by = blockIdx.y;  // k tile
    int tx = threadIdx.x; // 0..31
    for (int i = threadIdx.y; i < 32; i += 8)
        tile[i][tx] = W[(by * 32 + i) * HF + bx * 32 + tx];
    __syncthreads();
    int k = by * 32 + tx;
    for (int i = threadIdx.y; i < 32; i += 8) {
        float v = tile[tx][i];          // k_local = tx, n_local = i
        int n = bx * 32 + i;
        __nv_bfloat16 hi = __float2bfloat16_rn(v);
        float r = v - __bfloat162float(hi);
        __nv_bfloat16 lo = __float2bfloat16_rn(r);
        g_Wh[n * IN_FEATS + k] = hi;
        g_Wl[n * IN_FEATS + k] = lo;
    }
}

__global__ __launch_bounds__(256) void asplit_kernel(const float* __restrict__ feat)
{
    int i = blockIdx.x * 256 + threadIdx.x;     // one float4 per thread
    if (i >= N_NODES * IN_FEATS / 4) return;
    float4 v = ((const float4*)feat)[i];
    float f[4] = {v.x, v.y, v.z, v.w};
    uint32_t hw[2], lw[2];
    #pragma unroll
    for (int j = 0; j < 2; ++j) {
        float x0 = f[2*j], x1 = f[2*j+1];
        __nv_bfloat16 h0 = __float2bfloat16_rn(x0);
        __nv_bfloat16 h1 = __float2bfloat16_rn(x1);
        __nv_bfloat16 l0 = __float2bfloat16_rn(x0 - __bfloat162float(h0));
        __nv_bfloat16 l1 = __float2bfloat16_rn(x1 - __bfloat162float(h1));
        hw[j] = ((uint32_t)__bfloat16_as_ushort(h1) << 16) | __bfloat16_as_ushort(h0);
        lw[j] = ((uint32_t)__bfloat16_as_ushort(l1) << 16) | __bfloat16_as_ushort(l0);
    }
    ((uint2*)g_Ah)[i] = make_uint2(hw[0], hw[1]);
    ((uint2*)g_Al)[i] = make_uint2(lw[0], lw[1]);
}

// ============== HMMA bf16x3 GEMM: h = feat @ W ================================
// CTA tile 128x128, BK=32 (bf16). 8 warps: 2(M) x 4(N), warp tile 64x32.
#define BM 128
#define BN 128
#define BK 32
#define NCH (IN_FEATS / BK)        // 16
#define ROWB 80                    // 64B data + 16B pad (conflict-free ldmatrix)
#define ARR_BYTES (128 * ROWB)     // 10240
#define STAGE_BYTES (4 * ARR_BYTES)
#define SM_TOTAL (2 * STAGE_BYTES) // 81920

__global__ __launch_bounds__(256, 2) void gemm_hmma_kernel(void)
{
    extern __shared__ char smem[];
    uint32_t sb = smem_u32(smem);
    int tid = threadIdx.x;
    int w = tid >> 5;
    int l = tid & 31;
    int bm = blockIdx.y * BM;
    int bn = blockIdx.x * BN;
    int wm = (w >> 2) * 64;
    int wn = (w & 3) * 32;

    float acc[4][4][4];
    #pragma unroll
    for (int a = 0; a < 4; ++a)
        #pragma unroll
        for (int b = 0; b < 4; ++b)
            #pragma unroll
            for (int c = 0; c < 4; ++c) acc[a][b][c] = 0.f;

    // ---- chunk loader (cp.async) ----
    auto load_chunk = [&](int c, int s) {
        int k0 = c * BK;
        uint32_t sbase = sb + s * STAGE_BYTES;
        #pragma unroll
        for (int arr = 0; arr < 4; ++arr) {
            const __nv_bfloat16* gsrc =
                (arr == 0) ? g_Ah : (arr == 1) ? g_Al : (arr == 2) ? g_Wh : g_Wl;
            int base_row = (arr < 2) ? bm : bn;
            uint32_t soff = sbase + arr * ARR_BYTES;
            #pragma unroll
            for (int i = 0; i < 2; ++i) {
                int idx = tid + i * 256;       // 0..511
                int row = idx >> 2;
                int c16 = idx & 3;
                int grow = base_row + row;
                int sz = 16;
                if (arr < 2 && grow >= N_NODES) { grow = 0; sz = 0; }
                const void* gp = gsrc + (size_t)grow * IN_FEATS + k0 + c16 * 8;
                cp_async16(soff + row * ROWB + c16 * 16, gp, sz);
            }
        }
        cp_commit();
    };

    load_chunk(0, 0);

    int lr = l & 15;
    int kc = (l & 16) ? 8 : 0;

    for (int c = 0; c < NCH; ++c) {
        if (c + 1 < NCH) load_chunk(c + 1, (c + 1) & 1);
        if (c + 1 < NCH) cp_wait<1>(); else cp_wait<0>();
        __syncthreads();

        uint32_t sA_h = sb + (c & 1) * STAGE_BYTES;
        uint32_t sA_l = sA_h + ARR_BYTES;
        uint32_t sB_h = sA_h + 2 * ARR_BYTES;
        uint32_t sB_l = sA_h + 3 * ARR_BYTES;

        #pragma unroll
        for (int ks = 0; ks < 2; ++ks) {
            uint32_t koff = (ks * 16 + kc) * 2;
            // B fragments: 4 n8 frags (hi + lo)
            uint32_t bh[4][2], bl[4][2];
            #pragma unroll
            for (int g = 0; g < 2; ++g) {
                uint32_t r[4];
                ldsm4(r, sB_h + (uint32_t)(wn + g * 16 + lr) * ROWB + koff);
                bh[2*g][0] = r[0]; bh[2*g+1][0] = r[1];
                bh[2*g][1] = r[2]; bh[2*g+1][1] = r[3];
                ldsm4(r, sB_l + (uint32_t)(wn + g * 16 + lr) * ROWB + koff);
                bl[2*g][0] = r[0]; bl[2*g+1][0] = r[1];
                bl[2*g][1] = r[2]; bl[2*g+1][1] = r[3];
            }
            #pragma unroll
            for (int fm = 0; fm < 4; ++fm) {
                uint32_t ah[4], al4[4];
                ldsm4(ah,  sA_h + (uint32_t)(wm + fm * 16 + lr) * ROWB + koff);
                ldsm4(al4, sA_l + (uint32_t)(wm + fm * 16 + lr) * ROWB + koff);
                #pragma unroll
                for (int fn = 0; fn < 4; ++fn) {
                    mma16816(acc[fm][fn], ah,  bh[fn]);
                    mma16816(acc[fm][fn], ah,  bl[fn]);
                    mma16816(acc[fm][fn], al4, bh[fn]);
                }
            }
        }
        __syncthreads();
    }

    // ---- epilogue: direct stores (32B sectors fully covered) ----
    #pragma unroll
    for (int fm = 0; fm < 4; ++fm) {
        int r0 = bm + wm + fm * 16 + (l >> 2);
        int r1 = r0 + 8;
        #pragma unroll
        for (int fn = 0; fn < 4; ++fn) {
            int col = bn + wn + fn * 8 + (l & 3) * 2;
            if (r0 < N_NODES)
                *(float2*)(g_h + (size_t)r0 * HF + col) =
                    make_float2(acc[fm][fn][0], acc[fm][fn][1]);
            if (r1 < N_NODES)
                *(float2*)(g_h + (size_t)r1 * HF + col) =
                    make_float2(acc[fm][fn][2], acc[fm][fn][3]);
        }
    }
}

// -------------- el/er: per-(node,head) dot with attn_l / attn_r --------------
__global__ __launch_bounds__(256) void attn_dots_kernel(
    const float* __restrict__ h,
    const float* __restrict__ al,
    const float* __restrict__ ar,
    float* __restrict__ el,
    float* __restrict__ er)
{
    int n = blockIdx.x;
    int hd = threadIdx.x >> 5;
    int lane = threadIdx.x & 31;

    const float* hp = h + (size_t)n * HF + hd * OUT_FEATS;
    float x0 = hp[lane];
    float x1 = hp[lane + 32];
    float lv = x0 * al[hd * OUT_FEATS + lane] + x1 * al[hd * OUT_FEATS + lane + 32];
    float rv = x0 * ar[hd * OUT_FEATS + lane] + x1 * ar[hd * OUT_FEATS + lane + 32];
    #pragma unroll
    for (int o = 16; o > 0; o >>= 1) {
        lv += __shfl_xor_sync(0xFFFFFFFFu, lv, o);
        rv += __shfl_xor_sync(0xFFFFFFFFu, rv, o);
    }
    if (lane == 0) {
        el[n * HEADS + hd] = lv;
        er[n * HEADS + hd] = rv;
    }
}

// ------------------------------ CSR building ---------------------------------
__global__ void zero_counts_kernel()
{
    int i = blockIdx.x * blockDim.x + threadIdx.x;
    if (i <= N_NODES) g_cnt[i] = 0;
    if (i < N_NODES)  g_cur[i] = 0;
}

__global__ void count_kernel(const int* __restrict__ dst)
{
    int e = blockIdx.x * blockDim.x + threadIdx.x;
    if (e < N_EDGES) atomicAdd(&g_cnt[dst[e]], 1);
}

#define SCAN_CHUNK 10
__global__ __launch_bounds__(1024) void scan_kernel()
{
    __shared__ int sh[1024];
    int t = threadIdx.x;
    int base = t * SCAN_CHUNK;
    int vloc[SCAN_CHUNK];
    int s = 0;
    #pragma unroll
    for (int j = 0; j < SCAN_CHUNK; j++) {
        int idx = base + j;
        int c = (idx < N_NODES) ? g_cnt[idx] : 0;
        vloc[j] = c;
        s += c;
    }
    sh[t] = s;
    __syncthreads();
    for (int d = 1; d < 1024; d <<= 1) {
        int add = (t >= d) ? sh[t - d] : 0;
        __syncthreads();
        sh[t] += add;
        __syncthreads();
    }
    int run = sh[t] - s;
    #pragma unroll
    for (int j = 0; j < SCAN_CHUNK; j++) {
        int idx = base + j;
        if (idx <= N_NODES) g_off[idx] = run;
        run += vloc[j];
    }
}

__global__ void fill_kernel(const int* __restrict__ dst)
{
    int e = blockIdx.x * blockDim.x + threadIdx.x;
    if (e < N_EDGES) {
        int d = dst[e];
        int pos = atomicAdd(&g_cur[d], 1);
        g_perm[g_off[d] + pos] = e;
    }
}

// ---------- softmax over incoming edges + weighted aggregation ---------------
__global__ __launch_bounds__(256) void aggregate_kernel(
    const int* __restrict__ src,
    const float* __restrict__ bias,
    float* __restrict__ out)
{
    int n = blockIdx.x;
    int hd = threadIdx.x >> 5;
    int lane = threadIdx.x & 31;

    int beg = g_off[n];
    int end = g_off[n + 1];
    float er_nh = g_er[n * HEADS + hd];

    float m = -INFINITY;
    for (int i = beg + lane; i < end; i += 32) {
        int e = g_perm[i];
        int s = src[e];
        float v = g_el[s * HEADS + hd] + er_nh;
        v = (v > 0.f) ? v : NEG_SLOPE * v;
        m = fmaxf(m, v);
    }
    #pragma unroll
    for (int o = 16; o > 0; o >>= 1)
        m = fmaxf(m, __shfl_xor_sync(0xFFFFFFFFu, m, o));

    float ssum = 0.f;
    for (int i = beg + lane; i < end; i += 32) {
        int e = g_perm[i];
        int s = src[e];
        float v = g_el[s * HEADS + hd] + er_nh;
        v = (v > 0.f) ? v : NEG_SLOPE * v;
        ssum += __expf(v - m);
    }
    #pragma unroll
    for (int o = 16; o > 0; o >>= 1)
        ssum += __shfl_xor_sync(0xFFFFFFFFu, ssum, o);

    float inv = (ssum > 0.f) ? (1.0f / ssum) : 0.f;

    float acc0 = 0.f, acc1 = 0.f;
    for (int i = beg; i < end; ++i) {
        int e = g_perm[i];
        int s = src[e];
        float v = g_el[s * HEADS + hd] + er_nh;
        v = (v > 0.f) ? v : NEG_SLOPE * v;
        float a = __expf(v - m) * inv;
        const float* hp = g_h + (size_t)s * HF + hd * OUT_FEATS;
        acc0 = fmaf(a, hp[lane], acc0);
        acc1 = fmaf(a, hp[lane + 32], acc1);
    }

    int ob = n * HF + hd * OUT_FEATS;
    out[ob + lane]      = acc0 + bias[hd * OUT_FEATS + lane];
    out[ob + lane + 32] = acc1 + bias[hd * OUT_FEATS + lane + 32];
}

// ------------------------------- launcher ------------------------------------
extern "C" void kernel_launch(void* const* d_in, const int* in_sizes, int n_in,
                              void* d_out, int out_size)
{
    const float* feat   = (const float*)d_in[0];  // [10000, 512]
    const float* W      = (const float*)d_in[1];  // [512, 512]
    const float* attn_l = (const float*)d_in[2];  // [8, 64]
    const float* attn_r = (const float*)d_in[3];  // [8, 64]
    const float* bias   = (const float*)d_in[4];  // [512]
    const int*   src    = (const int*)d_in[5];    // [160000]
    const int*   dst    = (const int*)d_in[6];    // [160000]
    float* out = (float*)d_out;                   // [10000, 8, 64]

    float* d_h;  cudaGetSymbolAddress((void**)&d_h, g_h);
    float* d_el; cudaGetSymbolAddress((void**)&d_el, g_el);
    float* d_er; cudaGetSymbolAddress((void**)&d_er, g_er);

    cudaFuncSetAttribute(gemm_hmma_kernel,
                         cudaFuncAttributeMaxDynamicSharedMemorySize, SM_TOTAL);

    // 0) hi/lo splits
    wsplit_kernel<<<dim3(16, 16), dim3(32, 8)>>>(W);
    asplit_kernel<<<(N_NODES * IN_FEATS / 4 + 255) / 256, 256>>>(feat);
    // 1) projection GEMM on tensor cores (bf16x3 via mma.sync)
    {
        dim3 grid(HF / BN, (N_NODES + BM - 1) / BM);  // (4, 79)
        gemm_hmma_kernel<<<grid, 256, SM_TOTAL>>>();
    }
    // 2) attention dot products
    attn_dots_kernel<<<N_NODES, 256>>>(d_h, attn_l, attn_r, d_el, d_er);
    // 3) CSR build
    zero_counts_kernel<<<(N_NODES + 256) / 256, 256>>>();
    count_kernel<<<(N_EDGES + 255) / 256, 256>>>(dst);
    scan_kernel<<<1, 1024>>>();
    fill_kernel<<<(N_EDGES + 255) / 256, 256>>>(dst);
    // 4) softmax + aggregation
    aggregate_kernel<<<N_NODES, 256>>>(src, bias, out);
}

// round 4
// speedup vs baseline: 1.4525x; 1.0351x over previous
#include <cuda_runtime.h>
#include <cuda_bf16.h>
#include <math.h>
#include <stdint.h>

// Problem constants
#define N_NODES   10000
#define N_EDGES   160000
#define IN_FEATS  512
#define HEADS     8
#define OUT_FEATS 64
#define HF        (HEADS * OUT_FEATS)   // 512
#define NEG_SLOPE 0.2f

// ---------------- scratch (device globals; no allocs allowed) ----------------
__device__ float g_h[N_NODES * HF];          // projected features [N, 512]
__device__ float g_el[N_NODES * HEADS];
__device__ float g_er[N_NODES * HEADS];
__device__ int   g_cnt[N_NODES + 1];
__device__ int   g_off[N_NODES + 1];
__device__ int   g_cur[N_NODES];
__device__ int   g_perm[N_EDGES];
__device__ __nv_bfloat16 g_Wh[HF * IN_FEATS];      // W^T hi: [n][k]
__device__ __nv_bfloat16 g_Wl[HF * IN_FEATS];      // W^T lo: [n][k]

// ------------------------------ PTX helpers ----------------------------------
__device__ __forceinline__ uint32_t smem_u32(const void* p) {
    uint32_t a;
    asm("{ .reg .u64 t; cvta.to.shared.u64 t, %1; cvt.u32.u64 %0, t; }"
        : "=r"(a) : "l"(p));
    return a;
}
__device__ __forceinline__ void cp_async16(uint32_t sa, const void* gp) {
    asm volatile("cp.async.cg.shared.global [%0], [%1], 16;"
                 :: "r"(sa), "l"(gp));
}
__device__ __forceinline__ void cp_commit() {
    asm volatile("cp.async.commit_group;" ::: "memory");
}
template <int N>
__device__ __forceinline__ void cp_wait() {
    asm volatile("cp.async.wait_group %0;" :: "n"(N) : "memory");
}
__device__ __forceinline__ void ldsm4(uint32_t* r, uint32_t addr) {
    asm volatile("ldmatrix.sync.aligned.m8n8.x4.shared.b16 {%0,%1,%2,%3}, [%4];"
                 : "=r"(r[0]), "=r"(r[1]), "=r"(r[2]), "=r"(r[3]) : "r"(addr));
}
__device__ __forceinline__ void mma16816(float* d, const uint32_t* a, const uint32_t* b) {
    asm volatile(
        "mma.sync.aligned.m16n8k16.row.col.f32.bf16.bf16.f32 "
        "{%0,%1,%2,%3}, {%4,%5,%6,%7}, {%8,%9}, {%0,%1,%2,%3};"
        : "+f"(d[0]), "+f"(d[1]), "+f"(d[2]), "+f"(d[3])
        : "r"(a[0]), "r"(a[1]), "r"(a[2]), "r"(a[3]), "r"(b[0]), "r"(b[1]));
}
__device__ __forceinline__ uint32_t pack_hi(float x0, float x1) {
    __nv_bfloat16 h0 = __float2bfloat16_rn(x0);
    __nv_bfloat16 h1 = __float2bfloat16_rn(x1);
    return ((uint32_t)__bfloat16_as_ushort(h1) << 16) | __bfloat16_as_ushort(h0);
}
__device__ __forceinline__ uint32_t pack_lo(float x0, float x1) {
    __nv_bfloat16 h0 = __float2bfloat16_rn(x0);
    __nv_bfloat16 h1 = __float2bfloat16_rn(x1);
    float r0 = x0 - __bfloat162float(h0);
    float r1 = x1 - __bfloat162float(h1);
    __nv_bfloat16 l0 = __float2bfloat16_rn(r0);
    __nv_bfloat16 l1 = __float2bfloat16_rn(r1);
    return ((uint32_t)__bfloat16_as_ushort(l1) << 16) | __bfloat16_as_ushort(l0);
}

// ============== W pre-pass: transpose + hi/lo split + zero counts ============
__global__ __launch_bounds__(256) void wsplit_kernel(const float* __restrict__ W)
{
    // fold CSR counter zeroing into this kernel (65536 threads total)
    {
        int bid = blockIdx.y * 16 + blockIdx.x;
        int gid = bid * 256 + threadIdx.y * 32 + threadIdx.x;
        if (gid <= N_NODES) g_cnt[gid] = 0;
        if (gid < N_NODES)  g_cur[gid] = 0;
    }
    __shared__ float tile[32][33];
    int bx = blockIdx.x;  // n tile
    int by = blockIdx.y;  // k tile
    int tx = threadIdx.x; // 0..31
    for (int i = threadIdx.y; i < 32; i += 8)
        tile[i][tx] = W[(by * 32 + i) * HF + bx * 32 + tx];
    __syncthreads();
    int k = by * 32 + tx;
    for (int i = threadIdx.y; i < 32; i += 8) {
        float v = tile[tx][i];          // k_local = tx, n_local = i
        int n = bx * 32 + i;
        __nv_bfloat16 hi = __float2bfloat16_rn(v);
        float r = v - __bfloat162float(hi);
        __nv_bfloat16 lo = __float2bfloat16_rn(r);
        g_Wh[n * IN_FEATS + k] = hi;
        g_Wl[n * IN_FEATS + k] = lo;
    }
}

// ============== HMMA bf16x3 GEMM + fused el/er ================================
// CTA tile 128x128, BK=32. 8 warps: 2(M) x 4(N), warp tile 64x32.
#define BM 128
#define BN 128
#define BK 32
#define NCH (IN_FEATS / BK)        // 16
#define ROWB 80                    // 64B data + 16B pad
#define ARR_BYTES (128 * ROWB)     // 10240
#define STAGE_BYTES (4 * ARR_BYTES)
#define SM_TOTAL (2 * STAGE_BYTES) // 81920

__global__ __launch_bounds__(256, 2) void gemm_hmma_kernel(
    const float* __restrict__ feat,
    const float* __restrict__ attn_l,   // flat [512] matching col order
    const float* __restrict__ attn_r)
{
    extern __shared__ char smem[];
    uint32_t sb = smem_u32(smem);
    int tid = threadIdx.x;
    int w = tid >> 5;
    int l = tid & 31;
    int bm = blockIdx.y * BM;
    int bn = blockIdx.x * BN;
    int wm = (w >> 2) * 64;
    int wn = (w & 3) * 32;

    float acc[4][4][4];
    #pragma unroll
    for (int a = 0; a < 4; ++a)
        #pragma unroll
        for (int b = 0; b < 4; ++b)
            #pragma unroll
            for (int c = 0; c < 4; ++c) acc[a][b][c] = 0.f;

    // A prefetch register buffer: 16 floats (128 rows x 32 k / 256 thr)
    float af[16];
    int arow = tid >> 1;          // 0..127
    int akseg = tid & 1;          // 0..1 (16 floats each)

    auto loadA_regs = [&](int c) {
        int grow = bm + arow;
        if (grow < N_NODES) {
            const float4* p = (const float4*)(feat + (size_t)grow * IN_FEATS
                                              + c * BK + akseg * 16);
            #pragma unroll
            for (int j = 0; j < 4; ++j) {
                float4 v = p[j];
                af[4*j+0] = v.x; af[4*j+1] = v.y; af[4*j+2] = v.z; af[4*j+3] = v.w;
            }
        } else {
            #pragma unroll
            for (int j = 0; j < 16; ++j) af[j] = 0.f;
        }
    };
    auto stsA = [&](int s) {
        uint32_t base = sb + s * STAGE_BYTES + (uint32_t)arow * ROWB + akseg * 32;
        uint32_t hw[8], lw[8];
        #pragma unroll
        for (int j = 0; j < 8; ++j) {
            hw[j] = pack_hi(af[2*j], af[2*j+1]);
            lw[j] = pack_lo(af[2*j], af[2*j+1]);
        }
        *(uint4*)(smem + (base - sb))                 = make_uint4(hw[0], hw[1], hw[2], hw[3]);
        *(uint4*)(smem + (base - sb) + 16)            = make_uint4(hw[4], hw[5], hw[6], hw[7]);
        *(uint4*)(smem + (base - sb) + ARR_BYTES)     = make_uint4(lw[0], lw[1], lw[2], lw[3]);
        *(uint4*)(smem + (base - sb) + ARR_BYTES + 16)= make_uint4(lw[4], lw[5], lw[6], lw[7]);
    };
    auto cpB = [&](int c, int s) {
        int k0 = c * BK;
        uint32_t sbase = sb + s * STAGE_BYTES + 2 * ARR_BYTES;
        #pragma unroll
        for (int arr = 0; arr < 2; ++arr) {
            const __nv_bfloat16* gsrc = arr ? g_Wl : g_Wh;
            uint32_t soff = sbase + arr * ARR_BYTES;
            #pragma unroll
            for (int i = 0; i < 2; ++i) {
                int idx = tid + i * 256;       // 0..511
                int row = idx >> 2;
                int c16 = idx & 3;
                const void* gp = gsrc + (size_t)(bn + row) * IN_FEATS + k0 + c16 * 8;
                cp_async16(soff + row * ROWB + c16 * 16, gp);
            }
        }
        cp_commit();
    };

    // prologue
    loadA_regs(0);
    stsA(0);
    cpB(0, 0);

    int lr = l & 15;
    int kc = (l & 16) ? 8 : 0;

    for (int c = 0; c < NCH; ++c) {
        bool has_next = (c + 1 < NCH);
        if (has_next) {
            loadA_regs(c + 1);
            cpB(c + 1, (c + 1) & 1);
        }
        if (has_next) cp_wait<1>(); else cp_wait<0>();
        __syncthreads();

        uint32_t sA_h = sb + (c & 1) * STAGE_BYTES;
        uint32_t sA_l = sA_h + ARR_BYTES;
        uint32_t sB_h = sA_h + 2 * ARR_BYTES;
        uint32_t sB_l = sA_h + 3 * ARR_BYTES;

        #pragma unroll
        for (int ks = 0; ks < 2; ++ks) {
            uint32_t koff = (ks * 16 + kc) * 2;
            uint32_t bh[4][2], bl[4][2];
            #pragma unroll
            for (int g = 0; g < 2; ++g) {
                uint32_t r[4];
                ldsm4(r, sB_h + (uint32_t)(wn + g * 16 + lr) * ROWB + koff);
                bh[2*g][0] = r[0]; bh[2*g+1][0] = r[1];
                bh[2*g][1] = r[2]; bh[2*g+1][1] = r[3];
                ldsm4(r, sB_l + (uint32_t)(wn + g * 16 + lr) * ROWB + koff);
                bl[2*g][0] = r[0]; bl[2*g+1][0] = r[1];
                bl[2*g][1] = r[2]; bl[2*g+1][1] = r[3];
            }
            #pragma unroll
            for (int fm = 0; fm < 4; ++fm) {
                uint32_t ah[4], al4[4];
                ldsm4(ah,  sA_h + (uint32_t)(wm + fm * 16 + lr) * ROWB + koff);
                ldsm4(al4, sA_l + (uint32_t)(wm + fm * 16 + lr) * ROWB + koff);
                #pragma unroll
                for (int fn = 0; fn < 4; ++fn) {
                    mma16816(acc[fm][fn], ah,  bh[fn]);
                    mma16816(acc[fm][fn], ah,  bl[fn]);
                    mma16816(acc[fm][fn], al4, bh[fn]);
                }
            }
        }
        __syncthreads();
        if (has_next) stsA((c + 1) & 1);
    }

    // ---- epilogue 1: h stores (direct, 32B sectors covered) ----
    #pragma unroll
    for (int fm = 0; fm < 4; ++fm) {
        int r0 = bm + wm + fm * 16 + (l >> 2);
        int r1 = r0 + 8;
        #pragma unroll
        for (int fn = 0; fn < 4; ++fn) {
            int col = bn + wn + fn * 8 + (l & 3) * 2;
            if (r0 < N_NODES)
                *(float2*)(g_h + (size_t)r0 * HF + col) =
                    make_float2(acc[fm][fn][0], acc[fm][fn][1]);
            if (r1 < N_NODES)
                *(float2*)(g_h + (size_t)r1 * HF + col) =
                    make_float2(acc[fm][fn][2], acc[fm][fn][3]);
        }
    }

    // ---- epilogue 2: fused el/er (deterministic, no atomics) ----
    // partials: pel[row 128][wnidx 4], per[row 128][wnidx 4] in reused SMEM
    float* pel = (float*)smem;              // 128*4 floats = 2048B
    float* per = (float*)smem + 128 * 4;    // next 2048B

    // attn values for this thread's 8 columns
    float avl[8], avr[8];
    #pragma unroll
    for (int fn = 0; fn < 4; ++fn) {
        int colg = bn + wn + fn * 8 + (l & 3) * 2;
        avl[2*fn]   = attn_l[colg];
        avl[2*fn+1] = attn_l[colg + 1];
        avr[2*fn]   = attn_r[colg];
        avr[2*fn+1] = attn_r[colg + 1];
    }
    int wnidx = w & 3;
    #pragma unroll
    for (int fm = 0; fm < 4; ++fm) {
        float pl0 = 0.f, pl1 = 0.f, pr0 = 0.f, pr1 = 0.f;
        #pragma unroll
        for (int fn = 0; fn < 4; ++fn) {
            pl0 += acc[fm][fn][0] * avl[2*fn] + acc[fm][fn][1] * avl[2*fn+1];
            pl1 += acc[fm][fn][2] * avl[2*fn] + acc[fm][fn][3] * avl[2*fn+1];
            pr0 += acc[fm][fn][0] * avr[2*fn] + acc[fm][fn][1] * avr[2*fn+1];
            pr1 += acc[fm][fn][2] * avr[2*fn] + acc[fm][fn][3] * avr[2*fn+1];
        }
        // reduce over the 4 lanes that share a row (l&3)
        #pragma unroll
        for (int o = 1; o <= 2; o <<= 1) {
            pl0 += __shfl_xor_sync(0xFFFFFFFFu, pl0, o);
            pl1 += __shfl_xor_sync(0xFFFFFFFFu, pl1, o);
            pr0 += __shfl_xor_sync(0xFFFFFFFFu, pr0, o);
            pr1 += __shfl_xor_sync(0xFFFFFFFFu, pr1, o);
        }
        if ((l & 3) == 0) {
            int lr0 = wm + fm * 16 + (l >> 2);
            int lr1 = lr0 + 8;
            pel[lr0 * 4 + wnidx] = pl0;
            pel[lr1 * 4 + wnidx] = pl1;
            per[lr0 * 4 + wnidx] = pr0;
            per[lr1 * 4 + wnidx] = pr1;
        }
    }
    __syncthreads();
    // 256 threads: row = tid>>1 (128 rows), t = tid&1 (head in tile)
    {
        int row = tid >> 1;
        int t = tid & 1;
        int grow = bm + row;
        if (grow < N_NODES) {
            float el = pel[row * 4 + 2 * t] + pel[row * 4 + 2 * t + 1];
            float er = per[row * 4 + 2 * t] + per[row * 4 + 2 * t + 1];
            int hd = blockIdx.x * 2 + t;
            g_el[grow * HEADS + hd] = el;
            g_er[grow * HEADS + hd] = er;
        }
    }
}

// ------------------------------ CSR building ---------------------------------
__global__ void count_kernel(const int* __restrict__ dst)
{
    int e = blockIdx.x * blockDim.x + threadIdx.x;
    if (e < N_EDGES) atomicAdd(&g_cnt[dst[e]], 1);
}

#define SCAN_CHUNK 10
__global__ __launch_bounds__(1024) void scan_kernel()
{
    __shared__ int sh[1024];
    int t = threadIdx.x;
    int base = t * SCAN_CHUNK;
    int vloc[SCAN_CHUNK];
    int s = 0;
    #pragma unroll
    for (int j = 0; j < SCAN_CHUNK; j++) {
        int idx = base + j;
        int c = (idx < N_NODES) ? g_cnt[idx] : 0;
        vloc[j] = c;
        s += c;
    }
    sh[t] = s;
    __syncthreads();
    for (int d = 1; d < 1024; d <<= 1) {
        int add = (t >= d) ? sh[t - d] : 0;
        __syncthreads();
        sh[t] += add;
        __syncthreads();
    }
    int run = sh[t] - s;
    #pragma unroll
    for (int j = 0; j < SCAN_CHUNK; j++) {
        int idx = base + j;
        if (idx <= N_NODES) g_off[idx] = run;
        run += vloc[j];
    }
}

__global__ void fill_kernel(const int* __restrict__ dst)
{
    int e = blockIdx.x * blockDim.x + threadIdx.x;
    if (e < N_EDGES) {
        int d = dst[e];
        int pos = atomicAdd(&g_cur[d], 1);
        g_perm[g_off[d] + pos] = e;
    }
}

// ---------- softmax over incoming edges + weighted aggregation ---------------
__global__ __launch_bounds__(256) void aggregate_kernel(
    const int* __restrict__ src,
    const float* __restrict__ bias,
    float* __restrict__ out)
{
    int n = blockIdx.x;
    int hd = threadIdx.x >> 5;
    int lane = threadIdx.x & 31;

    int beg = g_off[n];
    int end = g_off[n + 1];
    float er_nh = g_er[n * HEADS + hd];

    float m = -INFINITY;
    for (int i = beg + lane; i < end; i += 32) {
        int e = g_perm[i];
        int s = src[e];
        float v = g_el[s * HEADS + hd] + er_nh;
        v = (v > 0.f) ? v : NEG_SLOPE * v;
        m = fmaxf(m, v);
    }
    #pragma unroll
    for (int o = 16; o > 0; o >>= 1)
        m = fmaxf(m, __shfl_xor_sync(0xFFFFFFFFu, m, o));

    float ssum = 0.f;
    for (int i = beg + lane; i < end; i += 32) {
        int e = g_perm[i];
        int s = src[e];
        float v = g_el[s * HEADS + hd] + er_nh;
        v = (v > 0.f) ? v : NEG_SLOPE * v;
        ssum += __expf(v - m);
    }
    #pragma unroll
    for (int o = 16; o > 0; o >>= 1)
        ssum += __shfl_xor_sync(0xFFFFFFFFu, ssum, o);

    float inv = (ssum > 0.f) ? (1.0f / ssum) : 0.f;

    float acc0 = 0.f, acc1 = 0.f;
    for (int i = beg; i < end; ++i) {
        int e = g_perm[i];
        int s = src[e];
        float v = g_el[s * HEADS + hd] + er_nh;
        v = (v > 0.f) ? v : NEG_SLOPE * v;
        float a = __expf(v - m) * inv;
        const float* hp = g_h + (size_t)s * HF + hd * OUT_FEATS;
        acc0 = fmaf(a, hp[lane], acc0);
        acc1 = fmaf(a, hp[lane + 32], acc1);
    }

    int ob = n * HF + hd * OUT_FEATS;
    out[ob + lane]      = acc0 + bias[hd * OUT_FEATS + lane];
    out[ob + lane + 32] = acc1 + bias[hd * OUT_FEATS + lane + 32];
}

// ------------------------------- launcher ------------------------------------
extern "C" void kernel_launch(void* const* d_in, const int* in_sizes, int n_in,
                              void* d_out, int out_size)
{
    const float* feat   = (const float*)d_in[0];  // [10000, 512]
    const float* W      = (const float*)d_in[1];  // [512, 512]
    const float* attn_l = (const float*)d_in[2];  // [8, 64] flat = [512]
    const float* attn_r = (const float*)d_in[3];  // [8, 64]
    const float* bias   = (const float*)d_in[4];  // [512]
    const int*   src    = (const int*)d_in[5];    // [160000]
    const int*   dst    = (const int*)d_in[6];    // [160000]
    float* out = (float*)d_out;                   // [10000, 8, 64]

    cudaFuncSetAttribute(gemm_hmma_kernel,
                         cudaFuncAttributeMaxDynamicSharedMemorySize, SM_TOTAL);

    // 0) W split (+ zero CSR counters)
    wsplit_kernel<<<dim3(16, 16), dim3(32, 8)>>>(W);
    // 1) CSR build
    count_kernel<<<(N_EDGES + 255) / 256, 256>>>(dst);
    scan_kernel<<<1, 1024>>>();
    fill_kernel<<<(N_EDGES + 255) / 256, 256>>>(dst);
    // 2) projection GEMM + fused el/er
    {
        dim3 grid(HF / BN, (N_NODES + BM - 1) / BM);  // (4, 79)
        gemm_hmma_kernel<<<grid, 256, SM_TOTAL>>>(feat, attn_l, attn_r);
    }
    // 3) softmax + aggregation
    aggregate_kernel<<<N_NODES, 256>>>(src, bias, out);
}

// round 5
// speedup vs baseline: 1.8440x; 1.2695x over previous
#include <cuda_runtime.h>
#include <cuda_bf16.h>
#include <math.h>
#include <stdint.h>

// Problem constants
#define N_NODES   10000
#define N_EDGES   160000
#define IN_FEATS  512
#define HEADS     8
#define OUT_FEATS 64
#define HF        (HEADS * OUT_FEATS)   // 512
#define NEG_SLOPE 0.2f

// ---------------- scratch (device globals; no allocs allowed) ----------------
__device__ float g_h[N_NODES * HF];
__device__ float g_el[N_NODES * HEADS];
__device__ float g_er[N_NODES * HEADS];
__device__ int   g_cnt[N_NODES + 1];
__device__ int   g_off[N_NODES + 1];
__device__ int   g_cur[N_NODES];
__device__ int   g_perm[N_EDGES];
__device__ int   g_tile;
__device__ __nv_bfloat16 g_Wh[HF * IN_FEATS];      // W^T hi: [n][k]
__device__ __nv_bfloat16 g_Wl[HF * IN_FEATS];      // W^T lo: [n][k]

// ------------------------------ PTX helpers ----------------------------------
__device__ __forceinline__ uint32_t smem_u32(const void* p) {
    uint32_t a;
    asm("{ .reg .u64 t; cvta.to.shared.u64 t, %1; cvt.u32.u64 %0, t; }"
        : "=r"(a) : "l"(p));
    return a;
}
__device__ __forceinline__ void cp_async16(uint32_t sa, const void* gp) {
    asm volatile("cp.async.cg.shared.global [%0], [%1], 16;"
                 :: "r"(sa), "l"(gp));
}
__device__ __forceinline__ void cp_commit() {
    asm volatile("cp.async.commit_group;" ::: "memory");
}
template <int N>
__device__ __forceinline__ void cp_wait() {
    asm volatile("cp.async.wait_group %0;" :: "n"(N) : "memory");
}
__device__ __forceinline__ void ldsm4(uint32_t* r, uint32_t addr) {
    asm volatile("ldmatrix.sync.aligned.m8n8.x4.shared.b16 {%0,%1,%2,%3}, [%4];"
                 : "=r"(r[0]), "=r"(r[1]), "=r"(r[2]), "=r"(r[3]) : "r"(addr));
}
__device__ __forceinline__ void mma16816(float* d, const uint32_t* a, const uint32_t* b) {
    asm volatile(
        "mma.sync.aligned.m16n8k16.row.col.f32.bf16.bf16.f32 "
        "{%0,%1,%2,%3}, {%4,%5,%6,%7}, {%8,%9}, {%0,%1,%2,%3};"
        : "+f"(d[0]), "+f"(d[1]), "+f"(d[2]), "+f"(d[3])
        : "r"(a[0]), "r"(a[1]), "r"(a[2]), "r"(a[3]), "r"(b[0]), "r"(b[1]));
}
__device__ __forceinline__ uint32_t pack_hi(float x0, float x1) {
    __nv_bfloat16 h0 = __float2bfloat16_rn(x0);
    __nv_bfloat16 h1 = __float2bfloat16_rn(x1);
    return ((uint32_t)__bfloat16_as_ushort(h1) << 16) | __bfloat16_as_ushort(h0);
}
__device__ __forceinline__ uint32_t pack_lo(float x0, float x1) {
    __nv_bfloat16 h0 = __float2bfloat16_rn(x0);
    __nv_bfloat16 h1 = __float2bfloat16_rn(x1);
    float r0 = x0 - __bfloat162float(h0);
    float r1 = x1 - __bfloat162float(h1);
    __nv_bfloat16 l0 = __float2bfloat16_rn(r0);
    __nv_bfloat16 l1 = __float2bfloat16_rn(r1);
    return ((uint32_t)__bfloat16_as_ushort(l1) << 16) | __bfloat16_as_ushort(l0);
}

// ============== W pre-pass: transpose + hi/lo split + resets ==================
__global__ __launch_bounds__(256) void wsplit_kernel(const float* __restrict__ W)
{
    if (blockIdx.x == 0 && blockIdx.y == 0 && threadIdx.x == 0 && threadIdx.y == 0)
        g_tile = 0;
    {
        int bid = blockIdx.y * 16 + blockIdx.x;
        int gid = bid * 256 + threadIdx.y * 32 + threadIdx.x;
        if (gid <= N_NODES) g_cnt[gid] = 0;
        if (gid < N_NODES)  g_cur[gid] = 0;
    }
    __shared__ float tile[32][33];
    int bx = blockIdx.x;  // n tile
    int by = blockIdx.y;  // k tile
    int tx = threadIdx.x;
    for (int i = threadIdx.y; i < 32; i += 8)
        tile[i][tx] = W[(by * 32 + i) * HF + bx * 32 + tx];
    __syncthreads();
    int k = by * 32 + tx;
    for (int i = threadIdx.y; i < 32; i += 8) {
        float v = tile[tx][i];
        int n = bx * 32 + i;
        __nv_bfloat16 hi = __float2bfloat16_rn(v);
        float r = v - __bfloat162float(hi);
        __nv_bfloat16 lo = __float2bfloat16_rn(r);
        g_Wh[n * IN_FEATS + k] = hi;
        g_Wl[n * IN_FEATS + k] = lo;
    }
}

// ============== persistent HMMA bf16x3 GEMM + fused el/er =====================
// Tile 64(M) x 128(N), BK=32, 8 warps: 2(M) x 4(N), warp tile 32x32.
// Dynamic tile ticketing over a fixed 296-CTA grid (1 wave at occ 2).
#define BM 64
#define BN 128
#define BK 32
#define NCH (IN_FEATS / BK)        // 16
#define ROWB 80                    // 64B data + 16B pad
#define A_BYTES (BM * ROWB)        // 5120
#define B_BYTES (BN * ROWB)        // 10240
#define STAGE_BYTES (2 * A_BYTES + 2 * B_BYTES)   // 30720
#define SM_TOTAL (2 * STAGE_BYTES)                // 61440
#define MT_TILES 157               // ceil(10000/64)
#define NT_TILES 4
#define NTILES (MT_TILES * NT_TILES)   // 628
#define GRID_GEMM 296

__global__ __launch_bounds__(256, 2) void gemm_hmma_kernel(
    const float* __restrict__ feat,
    const float* __restrict__ attn_l,
    const float* __restrict__ attn_r)
{
    extern __shared__ char smem[];
    __shared__ int sh_tile;
    uint32_t sb = smem_u32(smem);
    int tid = threadIdx.x;
    int w = tid >> 5;
    int l = tid & 31;
    int wm = (w >> 2) * 32;
    int wn = (w & 3) * 32;
    int lr = l & 15;
    int kc = (l & 16) ? 8 : 0;
    int arow = tid >> 2;          // 0..63
    int akseg = tid & 3;          // 8 floats each

    for (;;) {
        if (tid == 0) sh_tile = atomicAdd(&g_tile, 1);
        __syncthreads();
        int t = sh_tile;
        if (t >= NTILES) break;
        int bm = (t >> 2) * BM;
        int bn = (t & 3) * BN;

        float acc[2][4][4];
        #pragma unroll
        for (int a = 0; a < 2; ++a)
            #pragma unroll
            for (int b = 0; b < 4; ++b)
                #pragma unroll
                for (int c = 0; c < 4; ++c) acc[a][b][c] = 0.f;

        float af[8];
        auto loadA_regs = [&](int c) {
            int grow = bm + arow;
            if (grow < N_NODES) {
                const float4* p = (const float4*)(feat + (size_t)grow * IN_FEATS
                                                  + c * BK + akseg * 8);
                float4 v0 = p[0], v1 = p[1];
                af[0]=v0.x; af[1]=v0.y; af[2]=v0.z; af[3]=v0.w;
                af[4]=v1.x; af[5]=v1.y; af[6]=v1.z; af[7]=v1.w;
            } else {
                #pragma unroll
                for (int j = 0; j < 8; ++j) af[j] = 0.f;
            }
        };
        auto stsA = [&](int s) {
            uint32_t off = s * STAGE_BYTES + (uint32_t)arow * ROWB + akseg * 16;
            uint32_t hw[4], lw[4];
            #pragma unroll
            for (int j = 0; j < 4; ++j) {
                hw[j] = pack_hi(af[2*j], af[2*j+1]);
                lw[j] = pack_lo(af[2*j], af[2*j+1]);
            }
            *(uint4*)(smem + off)           = make_uint4(hw[0], hw[1], hw[2], hw[3]);
            *(uint4*)(smem + off + A_BYTES) = make_uint4(lw[0], lw[1], lw[2], lw[3]);
        };
        auto cpB = [&](int c, int s) {
            int k0 = c * BK;
            uint32_t sbase = sb + s * STAGE_BYTES + 2 * A_BYTES;
            #pragma unroll
            for (int arr = 0; arr < 2; ++arr) {
                const __nv_bfloat16* gsrc = arr ? g_Wl : g_Wh;
                uint32_t soff = sbase + arr * B_BYTES;
                #pragma unroll
                for (int i = 0; i < 2; ++i) {
                    int idx = tid + i * 256;       // 0..511
                    int row = idx >> 2;
                    int c16 = idx & 3;
                    const void* gp = gsrc + (size_t)(bn + row) * IN_FEATS + k0 + c16 * 8;
                    cp_async16(soff + row * ROWB + c16 * 16, gp);
                }
            }
            cp_commit();
        };

        loadA_regs(0);
        stsA(0);
        cpB(0, 0);

        for (int c = 0; c < NCH; ++c) {
            bool has_next = (c + 1 < NCH);
            if (has_next) {
                loadA_regs(c + 1);
                cpB(c + 1, (c + 1) & 1);
            }
            if (has_next) cp_wait<1>(); else cp_wait<0>();
            __syncthreads();

            uint32_t sA_h = sb + (c & 1) * STAGE_BYTES;
            uint32_t sA_l = sA_h + A_BYTES;
            uint32_t sB_h = sA_h + 2 * A_BYTES;
            uint32_t sB_l = sB_h + B_BYTES;

            #pragma unroll
            for (int ks = 0; ks < 2; ++ks) {
                uint32_t koff = (ks * 16 + kc) * 2;
                uint32_t bh[4][2], bl[4][2];
                #pragma unroll
                for (int g = 0; g < 2; ++g) {
                    uint32_t r[4];
                    ldsm4(r, sB_h + (uint32_t)(wn + g * 16 + lr) * ROWB + koff);
                    bh[2*g][0] = r[0]; bh[2*g+1][0] = r[1];
                    bh[2*g][1] = r[2]; bh[2*g+1][1] = r[3];
                    ldsm4(r, sB_l + (uint32_t)(wn + g * 16 + lr) * ROWB + koff);
                    bl[2*g][0] = r[0]; bl[2*g+1][0] = r[1];
                    bl[2*g][1] = r[2]; bl[2*g+1][1] = r[3];
                }
                #pragma unroll
                for (int fm = 0; fm < 2; ++fm) {
                    uint32_t ah[4], al4[4];
                    ldsm4(ah,  sA_h + (uint32_t)(wm + fm * 16 + lr) * ROWB + koff);
                    ldsm4(al4, sA_l + (uint32_t)(wm + fm * 16 + lr) * ROWB + koff);
                    #pragma unroll
                    for (int fn = 0; fn < 4; ++fn) {
                        mma16816(acc[fm][fn], ah,  bh[fn]);
                        mma16816(acc[fm][fn], ah,  bl[fn]);
                        mma16816(acc[fm][fn], al4, bh[fn]);
                    }
                }
            }
            __syncthreads();
            if (has_next) stsA((c + 1) & 1);
        }

        // ---- epilogue 1: h stores ----
        #pragma unroll
        for (int fm = 0; fm < 2; ++fm) {
            int r0 = bm + wm + fm * 16 + (l >> 2);
            int r1 = r0 + 8;
            #pragma unroll
            for (int fn = 0; fn < 4; ++fn) {
                int col = bn + wn + fn * 8 + (l & 3) * 2;
                if (r0 < N_NODES)
                    *(float2*)(g_h + (size_t)r0 * HF + col) =
                        make_float2(acc[fm][fn][0], acc[fm][fn][1]);
                if (r1 < N_NODES)
                    *(float2*)(g_h + (size_t)r1 * HF + col) =
                        make_float2(acc[fm][fn][2], acc[fm][fn][3]);
            }
        }

        // ---- epilogue 2: fused el/er (deterministic) ----
        float* pel = (float*)smem;              // 64*4 floats
        float* per = (float*)smem + BM * 4;
        float avl[8], avr[8];
        #pragma unroll
        for (int fn = 0; fn < 4; ++fn) {
            int colg = bn + wn + fn * 8 + (l & 3) * 2;
            avl[2*fn]   = attn_l[colg];
            avl[2*fn+1] = attn_l[colg + 1];
            avr[2*fn]   = attn_r[colg];
            avr[2*fn+1] = attn_r[colg + 1];
        }
        int wnidx = w & 3;
        #pragma unroll
        for (int fm = 0; fm < 2; ++fm) {
            float pl0 = 0.f, pl1 = 0.f, pr0 = 0.f, pr1 = 0.f;
            #pragma unroll
            for (int fn = 0; fn < 4; ++fn) {
                pl0 += acc[fm][fn][0] * avl[2*fn] + acc[fm][fn][1] * avl[2*fn+1];
                pl1 += acc[fm][fn][2] * avl[2*fn] + acc[fm][fn][3] * avl[2*fn+1];
                pr0 += acc[fm][fn][0] * avr[2*fn] + acc[fm][fn][1] * avr[2*fn+1];
                pr1 += acc[fm][fn][2] * avr[2*fn] + acc[fm][fn][3] * avr[2*fn+1];
            }
            #pragma unroll
            for (int o = 1; o <= 2; o <<= 1) {
                pl0 += __shfl_xor_sync(0xFFFFFFFFu, pl0, o);
                pl1 += __shfl_xor_sync(0xFFFFFFFFu, pl1, o);
                pr0 += __shfl_xor_sync(0xFFFFFFFFu, pr0, o);
                pr1 += __shfl_xor_sync(0xFFFFFFFFu, pr1, o);
            }
            if ((l & 3) == 0) {
                int lr0 = wm + fm * 16 + (l >> 2);
                int lr1 = lr0 + 8;
                pel[lr0 * 4 + wnidx] = pl0;
                pel[lr1 * 4 + wnidx] = pl1;
                per[lr0 * 4 + wnidx] = pr0;
                per[lr1 * 4 + wnidx] = pr1;
            }
        }
        __syncthreads();
        if (tid < 2 * BM) {
            int row = tid >> 1;
            int tt = tid & 1;
            int grow = bm + row;
            if (grow < N_NODES) {
                float el = pel[row * 4 + 2 * tt] + pel[row * 4 + 2 * tt + 1];
                float er = per[row * 4 + 2 * tt] + per[row * 4 + 2 * tt + 1];
                int hd = (t & 3) * 2 + tt;
                g_el[grow * HEADS + hd] = el;
                g_er[grow * HEADS + hd] = er;
            }
        }
        __syncthreads();   // protect pel/per before next tile's prologue writes
    }
}

// ------------------------------ CSR building ---------------------------------
__global__ void count_kernel(const int* __restrict__ dst)
{
    int e = blockIdx.x * blockDim.x + threadIdx.x;
    if (e < N_EDGES) atomicAdd(&g_cnt[dst[e]], 1);
}

#define SCAN_CHUNK 10
__global__ __launch_bounds__(1024) void scan_kernel()
{
    __shared__ int sh[1024];
    int t = threadIdx.x;
    int base = t * SCAN_CHUNK;
    int vloc[SCAN_CHUNK];
    int s = 0;
    #pragma unroll
    for (int j = 0; j < SCAN_CHUNK; j++) {
        int idx = base + j;
        int c = (idx < N_NODES) ? g_cnt[idx] : 0;
        vloc[j] = c;
        s += c;
    }
    sh[t] = s;
    __syncthreads();
    for (int d = 1; d < 1024; d <<= 1) {
        int add = (t >= d) ? sh[t - d] : 0;
        __syncthreads();
        sh[t] += add;
        __syncthreads();
    }
    int run = sh[t] - s;
    #pragma unroll
    for (int j = 0; j < SCAN_CHUNK; j++) {
        int idx = base + j;
        if (idx <= N_NODES) g_off[idx] = run;
        run += vloc[j];
    }
}

__global__ void fill_kernel(const int* __restrict__ dst)
{
    int e = blockIdx.x * blockDim.x + threadIdx.x;
    if (e < N_EDGES) {
        int d = dst[e];
        int pos = atomicAdd(&g_cur[d], 1);
        g_perm[g_off[d] + pos] = e;
    }
}

// ---------- softmax over incoming edges + weighted aggregation ---------------
// One block per dst node, one warp per head. Unnormalized accumulate, scale
// once at the end. Per-chunk coefficients staged in SMEM.
__global__ __launch_bounds__(256) void aggregate_kernel(
    const int* __restrict__ src,
    const float* __restrict__ bias,
    float* __restrict__ out)
{
    __shared__ float2 buf[8][32];   // (p, src-as-float) per warp
    int n = blockIdx.x;
    int hd = threadIdx.x >> 5;
    int lane = threadIdx.x & 31;

    int beg = g_off[n];
    int end = g_off[n + 1];
    float er_nh = g_er[n * HEADS + hd];

    // Pass 1: max
    float m = -INFINITY;
    for (int i = beg + lane; i < end; i += 32) {
        int e = g_perm[i];
        int s = src[e];
        float v = g_el[s * HEADS + hd] + er_nh;
        v = (v > 0.f) ? v : NEG_SLOPE * v;
        m = fmaxf(m, v);
    }
    #pragma unroll
    for (int o = 16; o > 0; o >>= 1)
        m = fmaxf(m, __shfl_xor_sync(0xFFFFFFFFu, m, o));

    // Chunked: compute p lane-parallel, then vector-accumulate from SMEM coeffs
    float ssum_l = 0.f;
    float acc0 = 0.f, acc1 = 0.f;
    for (int base = beg; base < end; base += 32) {
        int cnt = end - base; if (cnt > 32) cnt = 32;
        if (lane < cnt) {
            int e = g_perm[base + lane];
            int s = src[e];
            float v = g_el[s * HEADS + hd] + er_nh;
            v = (v > 0.f) ? v : NEG_SLOPE * v;
            float p = __expf(v - m);
            ssum_l += p;
            buf[hd][lane] = make_float2(p, __int_as_float(s));
        }
        __syncwarp();
        #pragma unroll 4
        for (int j = 0; j < cnt; ++j) {
            float2 ps = buf[hd][j];
            float p = ps.x;
            int s = __float_as_int(ps.y);
            const float2* hp = (const float2*)(g_h + (size_t)s * HF + hd * OUT_FEATS);
            float2 hv = hp[lane];
            acc0 = fmaf(p, hv.x, acc0);
            acc1 = fmaf(p, hv.y, acc1);
        }
        __syncwarp();
    }
    #pragma unroll
    for (int o = 16; o > 0; o >>= 1)
        ssum_l += __shfl_xor_sync(0xFFFFFFFFu, ssum_l, o);

    float inv = (ssum_l > 0.f) ? (1.0f / ssum_l) : 0.f;

    int ob = n * HF + hd * OUT_FEATS + 2 * lane;
    float b0 = bias[hd * OUT_FEATS + 2 * lane];
    float b1 = bias[hd * OUT_FEATS + 2 * lane + 1];
    *(float2*)(out + ob) = make_float2(acc0 * inv + b0, acc1 * inv + b1);
}

// ------------------------------- launcher ------------------------------------
extern "C" void kernel_launch(void* const* d_in, const int* in_sizes, int n_in,
                              void* d_out, int out_size)
{
    const float* feat   = (const float*)d_in[0];
    const float* W      = (const float*)d_in[1];
    const float* attn_l = (const float*)d_in[2];
    const float* attn_r = (const float*)d_in[3];
    const float* bias   = (const float*)d_in[4];
    const int*   src    = (const int*)d_in[5];
    const int*   dst    = (const int*)d_in[6];
    float* out = (float*)d_out;

    cudaFuncSetAttribute(gemm_hmma_kernel,
                         cudaFuncAttributeMaxDynamicSharedMemorySize, SM_TOTAL);

    // #1: W split (+ reset ticket + zero CSR counters)
    wsplit_kernel<<<dim3(16, 16), dim3(32, 8)>>>(W);
    // #2, #3: CSR count + scan
    count_kernel<<<(N_EDGES + 255) / 256, 256>>>(dst);
    scan_kernel<<<1, 1024>>>();
    // #4: persistent GEMM + fused el/er (lands in the profiled slot)
    gemm_hmma_kernel<<<GRID_GEMM, 256, SM_TOTAL>>>(feat, attn_l, attn_r);
    // #5: CSR fill
    fill_kernel<<<(N_EDGES + 255) / 256, 256>>>(dst);
    // #6: softmax + aggregation
    aggregate_kernel<<<N_NODES, 256>>>(src, bias, out);
}

// round 6
// speedup vs baseline: 1.9339x; 1.0488x over previous
#include <cuda_runtime.h>
#include <cuda_bf16.h>
#include <cuda_fp16.h>
#include <math.h>
#include <stdint.h>

// Problem constants
#define N_NODES   10000
#define N_EDGES   160000
#define IN_FEATS  512
#define HEADS     8
#define OUT_FEATS 64
#define HF        (HEADS * OUT_FEATS)   // 512
#define NEG_SLOPE 0.2f

// ---------------- scratch (device globals; no allocs allowed) ----------------
__device__ __half g_hh[N_NODES * HF];        // projected features, fp16
__device__ float g_el[N_NODES * HEADS];
__device__ float g_er[N_NODES * HEADS];
__device__ int   g_cnt[N_NODES + 1];
__device__ int   g_off[N_NODES + 1];
__device__ int   g_cur[N_NODES];
__device__ int   g_srcp[N_EDGES];            // src node per CSR slot
__device__ float g_e[N_EDGES * HEADS];       // leaky logits per CSR slot
__device__ int   g_tile;
__device__ __nv_bfloat16 g_Wh[HF * IN_FEATS];      // W^T hi: [n][k]
__device__ __nv_bfloat16 g_Wl[HF * IN_FEATS];      // W^T lo: [n][k]

// ------------------------------ PTX helpers ----------------------------------
__device__ __forceinline__ uint32_t smem_u32(const void* p) {
    uint32_t a;
    asm("{ .reg .u64 t; cvta.to.shared.u64 t, %1; cvt.u32.u64 %0, t; }"
        : "=r"(a) : "l"(p));
    return a;
}
__device__ __forceinline__ void cp_async16(uint32_t sa, const void* gp) {
    asm volatile("cp.async.cg.shared.global [%0], [%1], 16;"
                 :: "r"(sa), "l"(gp));
}
__device__ __forceinline__ void cp_commit() {
    asm volatile("cp.async.commit_group;" ::: "memory");
}
template <int N>
__device__ __forceinline__ void cp_wait() {
    asm volatile("cp.async.wait_group %0;" :: "n"(N) : "memory");
}
__device__ __forceinline__ void ldsm4(uint32_t* r, uint32_t addr) {
    asm volatile("ldmatrix.sync.aligned.m8n8.x4.shared.b16 {%0,%1,%2,%3}, [%4];"
                 : "=r"(r[0]), "=r"(r[1]), "=r"(r[2]), "=r"(r[3]) : "r"(addr));
}
__device__ __forceinline__ void mma16816(float* d, const uint32_t* a, const uint32_t* b) {
    asm volatile(
        "mma.sync.aligned.m16n8k16.row.col.f32.bf16.bf16.f32 "
        "{%0,%1,%2,%3}, {%4,%5,%6,%7}, {%8,%9}, {%0,%1,%2,%3};"
        : "+f"(d[0]), "+f"(d[1]), "+f"(d[2]), "+f"(d[3])
        : "r"(a[0]), "r"(a[1]), "r"(a[2]), "r"(a[3]), "r"(b[0]), "r"(b[1]));
}
__device__ __forceinline__ uint32_t pack_hi(float x0, float x1) {
    __nv_bfloat16 h0 = __float2bfloat16_rn(x0);
    __nv_bfloat16 h1 = __float2bfloat16_rn(x1);
    return ((uint32_t)__bfloat16_as_ushort(h1) << 16) | __bfloat16_as_ushort(h0);
}
__device__ __forceinline__ uint32_t pack_lo(float x0, float x1) {
    __nv_bfloat16 h0 = __float2bfloat16_rn(x0);
    __nv_bfloat16 h1 = __float2bfloat16_rn(x1);
    float r0 = x0 - __bfloat162float(h0);
    float r1 = x1 - __bfloat162float(h1);
    __nv_bfloat16 l0 = __float2bfloat16_rn(r0);
    __nv_bfloat16 l1 = __float2bfloat16_rn(r1);
    return ((uint32_t)__bfloat16_as_ushort(l1) << 16) | __bfloat16_as_ushort(l0);
}

// ============== W pre-pass: transpose + hi/lo split + resets ==================
__global__ __launch_bounds__(256) void wsplit_kernel(const float* __restrict__ W)
{
    if (blockIdx.x == 0 && blockIdx.y == 0 && threadIdx.x == 0 && threadIdx.y == 0)
        g_tile = 0;
    {
        int bid = blockIdx.y * 16 + blockIdx.x;
        int gid = bid * 256 + threadIdx.y * 32 + threadIdx.x;
        if (gid <= N_NODES) g_cnt[gid] = 0;
        if (gid < N_NODES)  g_cur[gid] = 0;
    }
    __shared__ float tile[32][33];
    int bx = blockIdx.x;
    int by = blockIdx.y;
    int tx = threadIdx.x;
    for (int i = threadIdx.y; i < 32; i += 8)
        tile[i][tx] = W[(by * 32 + i) * HF + bx * 32 + tx];
    __syncthreads();
    int k = by * 32 + tx;
    for (int i = threadIdx.y; i < 32; i += 8) {
        float v = tile[tx][i];
        int n = bx * 32 + i;
        __nv_bfloat16 hi = __float2bfloat16_rn(v);
        float r = v - __bfloat162float(hi);
        __nv_bfloat16 lo = __float2bfloat16_rn(r);
        g_Wh[n * IN_FEATS + k] = hi;
        g_Wl[n * IN_FEATS + k] = lo;
    }
}

// ============== persistent HMMA bf16x3 GEMM + fused el/er =====================
// Tile 64(M) x 128(N), BK=32. 8 warps: 2(M) x 4(N), warp tile 32x32.
// A double-buffered (regs->STS), B 4-stage cp.async ring (prefetch dist 2).
#define BM 64
#define BN 128
#define BK 32
#define NCH (IN_FEATS / BK)        // 16
#define ROWB 80                    // 64B data + 16B pad
#define A_BYTES (BM * ROWB)        // 5120
#define B_BYTES (BN * ROWB)        // 10240
#define A_STAGE (2 * A_BYTES)      // hi+lo, 10240
#define B_STAGE (2 * B_BYTES)      // hi+lo, 20480
#define B_BASE  (2 * A_STAGE)      // 20480
#define SM_TOTAL (B_BASE + 4 * B_STAGE)   // 102400
#define MT_TILES 157
#define NT_TILES 4
#define NTILES (MT_TILES * NT_TILES)   // 628
#define GRID_GEMM 296

__global__ __launch_bounds__(256, 2) void gemm_hmma_kernel(
    const float* __restrict__ feat,
    const float* __restrict__ attn_l,
    const float* __restrict__ attn_r)
{
    extern __shared__ char smem[];
    __shared__ int sh_tile;
    uint32_t sb = smem_u32(smem);
    int tid = threadIdx.x;
    int w = tid >> 5;
    int l = tid & 31;
    int wm = (w >> 2) * 32;
    int wn = (w & 3) * 32;
    int lr = l & 15;
    int kc = (l & 16) ? 8 : 0;
    int arow = tid >> 2;          // 0..63
    int akseg = tid & 3;

    for (;;) {
        if (tid == 0) sh_tile = atomicAdd(&g_tile, 1);
        __syncthreads();
        int t = sh_tile;
        if (t >= NTILES) break;
        int bm = (t >> 2) * BM;
        int bn = (t & 3) * BN;

        float acc[2][4][4];
        #pragma unroll
        for (int a = 0; a < 2; ++a)
            #pragma unroll
            for (int b = 0; b < 4; ++b)
                #pragma unroll
                for (int c = 0; c < 4; ++c) acc[a][b][c] = 0.f;

        float af[8];
        auto loadA_regs = [&](int c) {
            int grow = bm + arow;
            if (grow < N_NODES) {
                const float4* p = (const float4*)(feat + (size_t)grow * IN_FEATS
                                                  + c * BK + akseg * 8);
                float4 v0 = p[0], v1 = p[1];
                af[0]=v0.x; af[1]=v0.y; af[2]=v0.z; af[3]=v0.w;
                af[4]=v1.x; af[5]=v1.y; af[6]=v1.z; af[7]=v1.w;
            } else {
                #pragma unroll
                for (int j = 0; j < 8; ++j) af[j] = 0.f;
            }
        };
        auto stsA = [&](int s) {
            uint32_t off = s * A_STAGE + (uint32_t)arow * ROWB + akseg * 16;
            uint32_t hw[4], lw[4];
            #pragma unroll
            for (int j = 0; j < 4; ++j) {
                hw[j] = pack_hi(af[2*j], af[2*j+1]);
                lw[j] = pack_lo(af[2*j], af[2*j+1]);
            }
            *(uint4*)(smem + off)           = make_uint4(hw[0], hw[1], hw[2], hw[3]);
            *(uint4*)(smem + off + A_BYTES) = make_uint4(lw[0], lw[1], lw[2], lw[3]);
        };
        auto cpB = [&](int c) {
            int k0 = c * BK;
            uint32_t sbase = sb + B_BASE + (c & 3) * B_STAGE;
            #pragma unroll
            for (int arr = 0; arr < 2; ++arr) {
                const __nv_bfloat16* gsrc = arr ? g_Wl : g_Wh;
                uint32_t soff = sbase + arr * B_BYTES;
                #pragma unroll
                for (int i = 0; i < 2; ++i) {
                    int idx = tid + i * 256;
                    int row = idx >> 2;
                    int c16 = idx & 3;
                    const void* gp = gsrc + (size_t)(bn + row) * IN_FEATS + k0 + c16 * 8;
                    cp_async16(soff + row * ROWB + c16 * 16, gp);
                }
            }
            cp_commit();
        };

        // prologue
        loadA_regs(0);
        stsA(0);
        cpB(0);
        cpB(1);

        for (int c = 0; c < NCH; ++c) {
            bool has_next = (c + 1 < NCH);
            if (has_next) loadA_regs(c + 1);       // LDG early, consumed at stsA below
            if (c + 2 < NCH) cpB(c + 2);
            if (c < NCH - 2)       cp_wait<2>();
            else if (c == NCH - 2) cp_wait<1>();
            else                   cp_wait<0>();
            __syncthreads();                        // one barrier per chunk

            uint32_t sA_h = sb + (c & 1) * A_STAGE;
            uint32_t sA_l = sA_h + A_BYTES;
            uint32_t sB_h = sb + B_BASE + (c & 3) * B_STAGE;
            uint32_t sB_l = sB_h + B_BYTES;

            #pragma unroll
            for (int ks = 0; ks < 2; ++ks) {
                uint32_t koff = (ks * 16 + kc) * 2;
                uint32_t bh[4][2], bl[4][2];
                #pragma unroll
                for (int g = 0; g < 2; ++g) {
                    uint32_t r[4];
                    ldsm4(r, sB_h + (uint32_t)(wn + g * 16 + lr) * ROWB + koff);
                    bh[2*g][0] = r[0]; bh[2*g+1][0] = r[1];
                    bh[2*g][1] = r[2]; bh[2*g+1][1] = r[3];
                    ldsm4(r, sB_l + (uint32_t)(wn + g * 16 + lr) * ROWB + koff);
                    bl[2*g][0] = r[0]; bl[2*g+1][0] = r[1];
                    bl[2*g][1] = r[2]; bl[2*g+1][1] = r[3];
                }
                #pragma unroll
                for (int fm = 0; fm < 2; ++fm) {
                    uint32_t ah[4], al4[4];
                    ldsm4(ah,  sA_h + (uint32_t)(wm + fm * 16 + lr) * ROWB + koff);
                    ldsm4(al4, sA_l + (uint32_t)(wm + fm * 16 + lr) * ROWB + koff);
                    #pragma unroll
                    for (int fn = 0; fn < 4; ++fn) {
                        mma16816(acc[fm][fn], ah,  bh[fn]);
                        mma16816(acc[fm][fn], ah,  bl[fn]);
                        mma16816(acc[fm][fn], al4, bh[fn]);
                    }
                }
            }
            // write next A stage after MMAs; visibility via next chunk's barrier.
            if (has_next) stsA((c + 1) & 1);
        }

        // ---- epilogue 1: h stores (fp16) ----
        #pragma unroll
        for (int fm = 0; fm < 2; ++fm) {
            int r0 = bm + wm + fm * 16 + (l >> 2);
            int r1 = r0 + 8;
            #pragma unroll
            for (int fn = 0; fn < 4; ++fn) {
                int col = bn + wn + fn * 8 + (l & 3) * 2;
                if (r0 < N_NODES)
                    *(__half2*)(g_hh + (size_t)r0 * HF + col) =
                        __floats2half2_rn(acc[fm][fn][0], acc[fm][fn][1]);
                if (r1 < N_NODES)
                    *(__half2*)(g_hh + (size_t)r1 * HF + col) =
                        __floats2half2_rn(acc[fm][fn][2], acc[fm][fn][3]);
            }
        }

        // ---- epilogue 2: fused el/er (deterministic) ----
        float* pel = (float*)smem;
        float* per = (float*)smem + BM * 4;
        float avl[8], avr[8];
        #pragma unroll
        for (int fn = 0; fn < 4; ++fn) {
            int colg = bn + wn + fn * 8 + (l & 3) * 2;
            avl[2*fn]   = attn_l[colg];
            avl[2*fn+1] = attn_l[colg + 1];
            avr[2*fn]   = attn_r[colg];
            avr[2*fn+1] = attn_r[colg + 1];
        }
        int wnidx = w & 3;
        __syncthreads();   // all MMA/smem reads done before reusing smem
        #pragma unroll
        for (int fm = 0; fm < 2; ++fm) {
            float pl0 = 0.f, pl1 = 0.f, pr0 = 0.f, pr1 = 0.f;
            #pragma unroll
            for (int fn = 0; fn < 4; ++fn) {
                pl0 += acc[fm][fn][0] * avl[2*fn] + acc[fm][fn][1] * avl[2*fn+1];
                pl1 += acc[fm][fn][2] * avl[2*fn] + acc[fm][fn][3] * avl[2*fn+1];
                pr0 += acc[fm][fn][0] * avr[2*fn] + acc[fm][fn][1] * avr[2*fn+1];
                pr1 += acc[fm][fn][2] * avr[2*fn] + acc[fm][fn][3] * avr[2*fn+1];
            }
            #pragma unroll
            for (int o = 1; o <= 2; o <<= 1) {
                pl0 += __shfl_xor_sync(0xFFFFFFFFu, pl0, o);
                pl1 += __shfl_xor_sync(0xFFFFFFFFu, pl1, o);
                pr0 += __shfl_xor_sync(0xFFFFFFFFu, pr0, o);
                pr1 += __shfl_xor_sync(0xFFFFFFFFu, pr1, o);
            }
            if ((l & 3) == 0) {
                int lr0 = wm + fm * 16 + (l >> 2);
                int lr1 = lr0 + 8;
                pel[lr0 * 4 + wnidx] = pl0;
                pel[lr1 * 4 + wnidx] = pl1;
                per[lr0 * 4 + wnidx] = pr0;
                per[lr1 * 4 + wnidx] = pr1;
            }
        }
        __syncthreads();
        if (tid < 2 * BM) {
            int row = tid >> 1;
            int tt = tid & 1;
            int grow = bm + row;
            if (grow < N_NODES) {
                float el = pel[row * 4 + 2 * tt] + pel[row * 4 + 2 * tt + 1];
                float er = per[row * 4 + 2 * tt] + per[row * 4 + 2 * tt + 1];
                int hd = (t & 3) * 2 + tt;
                g_el[grow * HEADS + hd] = el;
                g_er[grow * HEADS + hd] = er;
            }
        }
        __syncthreads();   // protect pel/per before next tile's prologue writes
    }
}

// ------------------------------ CSR building ---------------------------------
__global__ void count_kernel(const int* __restrict__ dst)
{
    int e = blockIdx.x * blockDim.x + threadIdx.x;
    if (e < N_EDGES) atomicAdd(&g_cnt[dst[e]], 1);
}

#define SCAN_CHUNK 10
__global__ __launch_bounds__(1024) void scan_kernel()
{
    __shared__ int sh[1024];
    int t = threadIdx.x;
    int base = t * SCAN_CHUNK;
    int vloc[SCAN_CHUNK];
    int s = 0;
    #pragma unroll
    for (int j = 0; j < SCAN_CHUNK; j++) {
        int idx = base + j;
        int c = (idx < N_NODES) ? g_cnt[idx] : 0;
        vloc[j] = c;
        s += c;
    }
    sh[t] = s;
    __syncthreads();
    for (int d = 1; d < 1024; d <<= 1) {
        int add = (t >= d) ? sh[t - d] : 0;
        __syncthreads();
        sh[t] += add;
        __syncthreads();
    }
    int run = sh[t] - s;
    #pragma unroll
    for (int j = 0; j < SCAN_CHUNK; j++) {
        int idx = base + j;
        if (idx <= N_NODES) g_off[idx] = run;
        run += vloc[j];
    }
}

// -------- fill CSR slots + precompute CSR-ordered leaky logits ----------------
__global__ __launch_bounds__(256) void fill_logits_kernel(
    const int* __restrict__ src, const int* __restrict__ dst)
{
    int e = blockIdx.x * blockDim.x + threadIdx.x;
    if (e >= N_EDGES) return;
    int d = dst[e];
    int s = src[e];
    int pos = atomicAdd(&g_cur[d], 1);
    int i = g_off[d] + pos;
    g_srcp[i] = s;
    float4 l0 = *(const float4*)&g_el[s * HEADS];
    float4 l1 = *(const float4*)&g_el[s * HEADS + 4];
    float4 r0 = *(const float4*)&g_er[d * HEADS];
    float4 r1 = *(const float4*)&g_er[d * HEADS + 4];
    float v[8] = {l0.x + r0.x, l0.y + r0.y, l0.z + r0.z, l0.w + r0.w,
                  l1.x + r1.x, l1.y + r1.y, l1.z + r1.z, l1.w + r1.w};
    #pragma unroll
    for (int h = 0; h < 8; ++h)
        v[h] = (v[h] > 0.f) ? v[h] : NEG_SLOPE * v[h];
    *(float4*)&g_e[i * HEADS]     = make_float4(v[0], v[1], v[2], v[3]);
    *(float4*)&g_e[i * HEADS + 4] = make_float4(v[4], v[5], v[6], v[7]);
}

// ---------- softmax over incoming edges + weighted aggregation ---------------
// One block per dst node, one warp per head. Reads CSR-ordered logits/src,
// fp16 h; unnormalized accumulate, scale once at the end.
__global__ __launch_bounds__(256) void aggregate_kernel(
    const float* __restrict__ bias,
    float* __restrict__ out)
{
    __shared__ float2 buf[8][32];   // (p, src-as-float)
    int n = blockIdx.x;
    int hd = threadIdx.x >> 5;
    int lane = threadIdx.x & 31;

    int beg = g_off[n];
    int end = g_off[n + 1];

    // Pass 1: max over CSR-contiguous logits
    float m = -INFINITY;
    for (int i = beg + lane; i < end; i += 32)
        m = fmaxf(m, g_e[i * HEADS + hd]);
    #pragma unroll
    for (int o = 16; o > 0; o >>= 1)
        m = fmaxf(m, __shfl_xor_sync(0xFFFFFFFFu, m, o));

    // Pass 2: chunked exp + vector accumulate
    float ssum = 0.f;
    float acc0 = 0.f, acc1 = 0.f;
    for (int base = beg; base < end; base += 32) {
        int cnt = end - base; if (cnt > 32) cnt = 32;
        if (lane < cnt) {
            int i = base + lane;
            float p = __expf(g_e[i * HEADS + hd] - m);
            ssum += p;
            buf[hd][lane] = make_float2(p, __int_as_float(g_srcp[i]));
        }
        __syncwarp();
        #pragma unroll 4
        for (int j = 0; j < cnt; ++j) {
            float2 ps = buf[hd][j];
            int s = __float_as_int(ps.y);
            __half2 hv = *(const __half2*)(g_hh + (size_t)s * HF + hd * OUT_FEATS + 2 * lane);
            float2 f = __half22float2(hv);
            acc0 = fmaf(ps.x, f.x, acc0);
            acc1 = fmaf(ps.x, f.y, acc1);
        }
        __syncwarp();
    }
    #pragma unroll
    for (int o = 16; o > 0; o >>= 1)
        ssum += __shfl_xor_sync(0xFFFFFFFFu, ssum, o);

    float inv = (ssum > 0.f) ? (1.0f / ssum) : 0.f;

    int ob = n * HF + hd * OUT_FEATS + 2 * lane;
    float b0 = bias[hd * OUT_FEATS + 2 * lane];
    float b1 = bias[hd * OUT_FEATS + 2 * lane + 1];
    *(float2*)(out + ob) = make_float2(acc0 * inv + b0, acc1 * inv + b1);
}

// ------------------------------- launcher ------------------------------------
extern "C" void kernel_launch(void* const* d_in, const int* in_sizes, int n_in,
                              void* d_out, int out_size)
{
    const float* feat   = (const float*)d_in[0];
    const float* W      = (const float*)d_in[1];
    const float* attn_l = (const float*)d_in[2];
    const float* attn_r = (const float*)d_in[3];
    const float* bias   = (const float*)d_in[4];
    const int*   src    = (const int*)d_in[5];
    const int*   dst    = (const int*)d_in[6];
    float* out = (float*)d_out;

    cudaFuncSetAttribute(gemm_hmma_kernel,
                         cudaFuncAttributeMaxDynamicSharedMemorySize, SM_TOTAL);

    // #1: W split (+ reset ticket + zero CSR counters)
    wsplit_kernel<<<dim3(16, 16), dim3(32, 8)>>>(W);
    // #2, #3: CSR count + scan
    count_kernel<<<(N_EDGES + 255) / 256, 256>>>(dst);
    scan_kernel<<<1, 1024>>>();
    // #4: persistent GEMM + fused el/er (profiled slot)
    gemm_hmma_kernel<<<GRID_GEMM, 256, SM_TOTAL>>>(feat, attn_l, attn_r);
    // #5: CSR fill + CSR-ordered leaky logits
    fill_logits_kernel<<<(N_EDGES + 255) / 256, 256>>>(src, dst);
    // #6: softmax + aggregation
    aggregate_kernel<<<N_NODES, 256>>>(bias, out);
}

// round 8
// speedup vs baseline: 2.1978x; 1.1365x over previous
#include <cuda_runtime.h>
#include <cuda_fp16.h>
#include <math.h>
#include <stdint.h>

// Problem constants
#define N_NODES   10000
#define N_EDGES   160000
#define IN_FEATS  512
#define HEADS     8
#define OUT_FEATS 64
#define HF        (HEADS * OUT_FEATS)   // 512
#define NEG_SLOPE 0.2f

// ---------------- scratch (device globals; no allocs allowed) ----------------
__device__ __half g_hh[N_NODES * HF];        // projected features, fp16
__device__ float g_el[N_NODES * HEADS];
__device__ float g_er[N_NODES * HEADS];
__device__ int   g_cnt[N_NODES + 1];
__device__ int   g_off[N_NODES + 1];
__device__ int   g_cur[N_NODES];
__device__ int   g_srcp[N_EDGES];            // src node per CSR slot
__device__ float g_e[N_EDGES * HEADS];       // leaky logits per CSR slot
__device__ int   g_tile;
__device__ __half g_W16[HF * IN_FEATS];      // W^T fp16: [n][k]
__device__ __half g_Ah16[N_NODES * IN_FEATS]; // feat fp16 hi: [m][k]
__device__ __half g_Al16[N_NODES * IN_FEATS]; // feat fp16 lo: [m][k]

// ------------------------------ PTX helpers ----------------------------------
__device__ __forceinline__ uint32_t smem_u32(const void* p) {
    uint32_t a;
    asm("{ .reg .u64 t; cvta.to.shared.u64 t, %1; cvt.u32.u64 %0, t; }"
        : "=r"(a) : "l"(p));
    return a;
}
__device__ __forceinline__ void cp_async16(uint32_t sa, const void* gp) {
    asm volatile("cp.async.cg.shared.global [%0], [%1], 16;"
                 :: "r"(sa), "l"(gp));
}
__device__ __forceinline__ void cp_async16z(uint32_t sa, const void* gp, int sz) {
    asm volatile("cp.async.cg.shared.global [%0], [%1], 16, %2;"
                 :: "r"(sa), "l"(gp), "r"(sz));
}
__device__ __forceinline__ void cp_commit() {
    asm volatile("cp.async.commit_group;" ::: "memory");
}
template <int N>
__device__ __forceinline__ void cp_wait() {
    asm volatile("cp.async.wait_group %0;" :: "n"(N) : "memory");
}
__device__ __forceinline__ void ldsm4(uint32_t* r, uint32_t addr) {
    asm volatile("ldmatrix.sync.aligned.m8n8.x4.shared.b16 {%0,%1,%2,%3}, [%4];"
                 : "=r"(r[0]), "=r"(r[1]), "=r"(r[2]), "=r"(r[3]) : "r"(addr));
}
__device__ __forceinline__ void mma16816(float* d, const uint32_t* a, const uint32_t* b) {
    asm volatile(
        "mma.sync.aligned.m16n8k16.row.col.f32.f16.f16.f32 "
        "{%0,%1,%2,%3}, {%4,%5,%6,%7}, {%8,%9}, {%0,%1,%2,%3};"
        : "+f"(d[0]), "+f"(d[1]), "+f"(d[2]), "+f"(d[3])
        : "r"(a[0]), "r"(a[1]), "r"(a[2]), "r"(a[3]), "r"(b[0]), "r"(b[1]));
}

// ============== pre-pass 1: W transpose to fp16 + resets ======================
__global__ __launch_bounds__(256) void wsplit_kernel(const float* __restrict__ W)
{
    if (blockIdx.x == 0 && blockIdx.y == 0 && threadIdx.x == 0 && threadIdx.y == 0)
        g_tile = 0;
    {
        int bid = blockIdx.y * 16 + blockIdx.x;
        int gid = bid * 256 + threadIdx.y * 32 + threadIdx.x;
        if (gid <= N_NODES) g_cnt[gid] = 0;
        if (gid < N_NODES)  g_cur[gid] = 0;
    }
    __shared__ float tile[32][33];
    int bx = blockIdx.x;
    int by = blockIdx.y;
    int tx = threadIdx.x;
    for (int i = threadIdx.y; i < 32; i += 8)
        tile[i][tx] = W[(by * 32 + i) * HF + bx * 32 + tx];
    __syncthreads();
    int k = by * 32 + tx;
    for (int i = threadIdx.y; i < 32; i += 8) {
        int n = bx * 32 + i;
        g_W16[n * IN_FEATS + k] = __float2half_rn(tile[tx][i]);
    }
}

// ============== pre-pass 2: feat -> fp16 hi/lo split ==========================
__global__ __launch_bounds__(256) void asplit_kernel(const float* __restrict__ feat)
{
    int i = blockIdx.x * 256 + threadIdx.x;     // one float4 per thread
    if (i >= N_NODES * IN_FEATS / 4) return;
    float4 v = ((const float4*)feat)[i];
    float f[4] = {v.x, v.y, v.z, v.w};
    __half h[4], lo[4];
    #pragma unroll
    for (int j = 0; j < 4; ++j) {
        h[j]  = __float2half_rn(f[j]);
        lo[j] = __float2half_rn(f[j] - __half2float(h[j]));
    }
    ((uint2*)g_Ah16)[i] = make_uint2(
        ((uint32_t)__half_as_ushort(h[1]) << 16) | __half_as_ushort(h[0]),
        ((uint32_t)__half_as_ushort(h[3]) << 16) | __half_as_ushort(h[2]));
    ((uint2*)g_Al16)[i] = make_uint2(
        ((uint32_t)__half_as_ushort(lo[1]) << 16) | __half_as_ushort(lo[0]),
        ((uint32_t)__half_as_ushort(lo[3]) << 16) | __half_as_ushort(lo[2]));
}

// ============== persistent HMMA fp16x2 GEMM + fused el/er =====================
// Tile 64(M) x 128(N), BK=32. 8 warps: 2(M) x 4(N), warp tile 32x32.
// 3-stage unified cp.async ring (Ah, Al, B), prefetch distance 2.
#define BM 64
#define BN 128
#define BK 32
#define NCH (IN_FEATS / BK)        // 16
#define ROWB 80                    // 64B data + 16B pad
#define AH_OFF 0
#define AL_OFF (BM * ROWB)               // 5120
#define B_OFF  (2 * BM * ROWB)           // 10240
#define STAGE_BYTES (B_OFF + BN * ROWB)  // 20480
#define SM_TOTAL (3 * STAGE_BYTES)       // 61440
#define MT_TILES 157
#define NT_TILES 4
#define NTILES (MT_TILES * NT_TILES)     // 628
#define GRID_GEMM 444

__global__ __launch_bounds__(256, 3) void gemm_hmma_kernel(
    const float* __restrict__ attn_l,
    const float* __restrict__ attn_r)
{
    extern __shared__ char smem[];
    __shared__ int sh_tile;
    uint32_t sb = smem_u32(smem);
    int tid = threadIdx.x;
    int w = tid >> 5;
    int l = tid & 31;
    int wm = (w >> 2) * 32;
    int wn = (w & 3) * 32;
    int lr = l & 15;
    int kc = (l & 16) ? 8 : 0;

    // precomputed ldsm row offsets (tile-invariant)
    uint32_t aoff0 = (uint32_t)(wm + lr) * ROWB;
    uint32_t aoff1 = (uint32_t)(wm + 16 + lr) * ROWB;
    uint32_t boff0 = (uint32_t)(wn + lr) * ROWB;
    uint32_t boff1 = (uint32_t)(wn + 16 + lr) * ROWB;
    // cp.async assignments (tile-invariant)
    int arow = tid >> 2;          // 0..63 (A)
    int ac16 = tid & 3;           // 16B segment within 64B row
    int brow0 = tid >> 1;         // 0..127 (B, 2 x 16B per thread)
    int bseg = (tid & 1) * 2;     // segments {0,1} or {2,3}

    for (;;) {
        if (tid == 0) sh_tile = atomicAdd(&g_tile, 1);
        __syncthreads();
        int t = sh_tile;
        if (t >= NTILES) break;
        int bm = (t >> 2) * BM;
        int bn = (t & 3) * BN;

        float acc[2][4][4];
        #pragma unroll
        for (int a = 0; a < 2; ++a)
            #pragma unroll
            for (int b = 0; b < 4; ++b)
                #pragma unroll
                for (int c = 0; c < 4; ++c) acc[a][b][c] = 0.f;

        int agrow = bm + arow;
        int asz = (agrow < N_NODES) ? 16 : 0;
        if (agrow >= N_NODES) agrow = 0;
        const __half* apH = g_Ah16 + (size_t)agrow * IN_FEATS + ac16 * 8;
        const __half* apL = g_Al16 + (size_t)agrow * IN_FEATS + ac16 * 8;
        const __half* bp0 = g_W16 + (size_t)(bn + brow0) * IN_FEATS + bseg * 8;
        uint32_t sA = (uint32_t)arow * ROWB + ac16 * 16;
        uint32_t sB = (uint32_t)brow0 * ROWB + bseg * 16;

        auto load_chunk = [&](int c) {
            int k0 = c * BK;
            uint32_t st = sb + (c % 3) * STAGE_BYTES;
            cp_async16z(st + AH_OFF + sA, apH + k0, asz);
            cp_async16z(st + AL_OFF + sA, apL + k0, asz);
            // two adjacent 16B segments per thread (bytes sB, sB+16)
            cp_async16(st + B_OFF + sB,      bp0 + k0);
            cp_async16(st + B_OFF + sB + 16, bp0 + k0 + 8);
            cp_commit();
        };

        load_chunk(0);
        load_chunk(1);

        for (int c = 0; c < NCH; ++c) {
            if (c < NCH - 1) cp_wait<1>(); else cp_wait<0>();
            __syncthreads();
            if (c + 2 < NCH) load_chunk(c + 2);   // stage (c+2)%3 == (c-1)%3, free

            uint32_t st = sb + (c % 3) * STAGE_BYTES;
            uint32_t sA_h = st + AH_OFF;
            uint32_t sA_l = st + AL_OFF;
            uint32_t sB_h = st + B_OFF;

            #pragma unroll
            for (int ks = 0; ks < 2; ++ks) {
                uint32_t koff = (ks * 16 + kc) * 2;
                uint32_t bh[4][2];
                {
                    uint32_t r[4];
                    ldsm4(r, sB_h + boff0 + koff);
                    bh[0][0] = r[0]; bh[1][0] = r[1];
                    bh[0][1] = r[2]; bh[1][1] = r[3];
                    ldsm4(r, sB_h + boff1 + koff);
                    bh[2][0] = r[0]; bh[3][0] = r[1];
                    bh[2][1] = r[2]; bh[3][1] = r[3];
                }
                #pragma unroll
                for (int fm = 0; fm < 2; ++fm) {
                    uint32_t aoff = fm ? aoff1 : aoff0;
                    uint32_t ah[4], al4[4];
                    ldsm4(ah,  sA_h + aoff + koff);
                    ldsm4(al4, sA_l + aoff + koff);
                    #pragma unroll
                    for (int fn = 0; fn < 4; ++fn) {
                        mma16816(acc[fm][fn], ah,  bh[fn]);
                        mma16816(acc[fm][fn], al4, bh[fn]);
                    }
                }
            }
        }

        // ---- epilogue 1: h stores (fp16) ----
        #pragma unroll
        for (int fm = 0; fm < 2; ++fm) {
            int r0 = bm + wm + fm * 16 + (l >> 2);
            int r1 = r0 + 8;
            #pragma unroll
            for (int fn = 0; fn < 4; ++fn) {
                int col = bn + wn + fn * 8 + (l & 3) * 2;
                if (r0 < N_NODES)
                    *(__half2*)(g_hh + (size_t)r0 * HF + col) =
                        __floats2half2_rn(acc[fm][fn][0], acc[fm][fn][1]);
                if (r1 < N_NODES)
                    *(__half2*)(g_hh + (size_t)r1 * HF + col) =
                        __floats2half2_rn(acc[fm][fn][2], acc[fm][fn][3]);
            }
        }

        // ---- epilogue 2: fused el/er (deterministic) ----
        float* pel = (float*)smem;
        float* per = (float*)smem + BM * 4;
        float avl[8], avr[8];
        #pragma unroll
        for (int fn = 0; fn < 4; ++fn) {
            int colg = bn + wn + fn * 8 + (l & 3) * 2;
            avl[2*fn]   = attn_l[colg];
            avl[2*fn+1] = attn_l[colg + 1];
            avr[2*fn]   = attn_r[colg];
            avr[2*fn+1] = attn_r[colg + 1];
        }
        int wnidx = w & 3;
        __syncthreads();   // mainloop smem reads done before reuse
        #pragma unroll
        for (int fm = 0; fm < 2; ++fm) {
            float pl0 = 0.f, pl1 = 0.f, pr0 = 0.f, pr1 = 0.f;
            #pragma unroll
            for (int fn = 0; fn < 4; ++fn) {
                pl0 += acc[fm][fn][0] * avl[2*fn] + acc[fm][fn][1] * avl[2*fn+1];
                pl1 += acc[fm][fn][2] * avl[2*fn] + acc[fm][fn][3] * avl[2*fn+1];
                pr0 += acc[fm][fn][0] * avr[2*fn] + acc[fm][fn][1] * avr[2*fn+1];
                pr1 += acc[fm][fn][2] * avr[2*fn] + acc[fm][fn][3] * avr[2*fn+1];
            }
            #pragma unroll
            for (int o = 1; o <= 2; o <<= 1) {
                pl0 += __shfl_xor_sync(0xFFFFFFFFu, pl0, o);
                pl1 += __shfl_xor_sync(0xFFFFFFFFu, pl1, o);
                pr0 += __shfl_xor_sync(0xFFFFFFFFu, pr0, o);
                pr1 += __shfl_xor_sync(0xFFFFFFFFu, pr1, o);
            }
            if ((l & 3) == 0) {
                int lr0 = wm + fm * 16 + (l >> 2);
                int lr1 = lr0 + 8;
                pel[lr0 * 4 + wnidx] = pl0;
                pel[lr1 * 4 + wnidx] = pl1;
                per[lr0 * 4 + wnidx] = pr0;
                per[lr1 * 4 + wnidx] = pr1;
            }
        }
        __syncthreads();
        if (tid < 2 * BM) {
            int row = tid >> 1;
            int tt = tid & 1;
            int grow = bm + row;
            if (grow < N_NODES) {
                float el = pel[row * 4 + 2 * tt] + pel[row * 4 + 2 * tt + 1];
                float er = per[row * 4 + 2 * tt] + per[row * 4 + 2 * tt + 1];
                int hd = (t & 3) * 2 + tt;
                g_el[grow * HEADS + hd] = el;
                g_er[grow * HEADS + hd] = er;
            }
        }
        __syncthreads();   // protect pel/per before next tile's prologue
    }
}

// ------------------------------ CSR building ---------------------------------
__global__ void count_kernel(const int* __restrict__ dst)
{
    int e = blockIdx.x * blockDim.x + threadIdx.x;
    if (e < N_EDGES) atomicAdd(&g_cnt[dst[e]], 1);
}

#define SCAN_CHUNK 10
__global__ __launch_bounds__(1024) void scan_kernel()
{
    __shared__ int sh[1024];
    int t = threadIdx.x;
    int base = t * SCAN_CHUNK;
    int vloc[SCAN_CHUNK];
    int s = 0;
    #pragma unroll
    for (int j = 0; j < SCAN_CHUNK; j++) {
        int idx = base + j;
        int c = (idx < N_NODES) ? g_cnt[idx] : 0;
        vloc[j] = c;
        s += c;
    }
    sh[t] = s;
    __syncthreads();
    for (int d = 1; d < 1024; d <<= 1) {
        int add = (t >= d) ? sh[t - d] : 0;
        __syncthreads();
        sh[t] += add;
        __syncthreads();
    }
    int run = sh[t] - s;
    #pragma unroll
    for (int j = 0; j < SCAN_CHUNK; j++) {
        int idx = base + j;
        if (idx <= N_NODES) g_off[idx] = run;
        run += vloc[j];
    }
}

// -------- fill CSR slots + precompute CSR-ordered leaky logits ----------------
__global__ __launch_bounds__(256) void fill_logits_kernel(
    const int* __restrict__ src, const int* __restrict__ dst)
{
    int e = blockIdx.x * blockDim.x + threadIdx.x;
    if (e >= N_EDGES) return;
    int d = dst[e];
    int s = src[e];
    int pos = atomicAdd(&g_cur[d], 1);
    int i = g_off[d] + pos;
    g_srcp[i] = s;
    float4 l0 = *(const float4*)&g_el[s * HEADS];
    float4 l1 = *(const float4*)&g_el[s * HEADS + 4];
    float4 r0 = *(const float4*)&g_er[d * HEADS];
    float4 r1 = *(const float4*)&g_er[d * HEADS + 4];
    float v[8] = {l0.x + r0.x, l0.y + r0.y, l0.z + r0.z, l0.w + r0.w,
                  l1.x + r1.x, l1.y + r1.y, l1.z + r1.z, l1.w + r1.w};
    #pragma unroll
    for (int h = 0; h < 8; ++h)
        v[h] = (v[h] > 0.f) ? v[h] : NEG_SLOPE * v[h];
    *(float4*)&g_e[i * HEADS]     = make_float4(v[0], v[1], v[2], v[3]);
    *(float4*)&g_e[i * HEADS + 4] = make_float4(v[4], v[5], v[6], v[7]);
}

// ---------- softmax over incoming edges + weighted aggregation ---------------
__global__ __launch_bounds__(256) void aggregate_kernel(
    const float* __restrict__ bias,
    float* __restrict__ out)
{
    __shared__ float2 buf[8][32];
    int n = blockIdx.x;
    int hd = threadIdx.x >> 5;
    int lane = threadIdx.x & 31;

    int beg = g_off[n];
    int end = g_off[n + 1];

    float m = -INFINITY;
    for (int i = beg + lane; i < end; i += 32)
        m = fmaxf(m, g_e[i * HEADS + hd]);
    #pragma unroll
    for (int o = 16; o > 0; o >>= 1)
        m = fmaxf(m, __shfl_xor_sync(0xFFFFFFFFu, m, o));

    float ssum = 0.f;
    float acc0 = 0.f, acc1 = 0.f;
    for (int base = beg; base < end; base += 32) {
        int cnt = end - base; if (cnt > 32) cnt = 32;
        if (lane < cnt) {
            int i = base + lane;
            float p = __expf(g_e[i * HEADS + hd] - m);
            ssum += p;
            buf[hd][lane] = make_float2(p, __int_as_float(g_srcp[i]));
        }
        __syncwarp();
        #pragma unroll 4
        for (int j = 0; j < cnt; ++j) {
            float2 ps = buf[hd][j];
            int s = __float_as_int(ps.y);
            __half2 hv = *(const __half2*)(g_hh + (size_t)s * HF + hd * OUT_FEATS + 2 * lane);
            float2 f = __half22float2(hv);
            acc0 = fmaf(ps.x, f.x, acc0);
            acc1 = fmaf(ps.x, f.y, acc1);
        }
        __syncwarp();
    }
    #pragma unroll
    for (int o = 16; o > 0; o >>= 1)
        ssum += __shfl_xor_sync(0xFFFFFFFFu, ssum, o);

    float inv = (ssum > 0.f) ? (1.0f / ssum) : 0.f;

    int ob = n * HF + hd * OUT_FEATS + 2 * lane;
    float b0 = bias[hd * OUT_FEATS + 2 * lane];
    float b1 = bias[hd * OUT_FEATS + 2 * lane + 1];
    *(float2*)(out + ob) = make_float2(acc0 * inv + b0, acc1 * inv + b1);
}

// ------------------------------- launcher ------------------------------------
extern "C" void kernel_launch(void* const* d_in, const int* in_sizes, int n_in,
                              void* d_out, int out_size)
{
    const float* feat   = (const float*)d_in[0];
    const float* W      = (const float*)d_in[1];
    const float* attn_l = (const float*)d_in[2];
    const float* attn_r = (const float*)d_in[3];
    const float* bias   = (const float*)d_in[4];
    const int*   src    = (const int*)d_in[5];
    const int*   dst    = (const int*)d_in[6];
    float* out = (float*)d_out;

    cudaFuncSetAttribute(gemm_hmma_kernel,
                         cudaFuncAttributeMaxDynamicSharedMemorySize, SM_TOTAL);

    // #1: W fp16 transpose (+ reset ticket + zero CSR counters)
    wsplit_kernel<<<dim3(16, 16), dim3(32, 8)>>>(W);
    // #2: CSR count
    count_kernel<<<(N_EDGES + 255) / 256, 256>>>(dst);
    // #3: feat fp16 hi/lo split
    asplit_kernel<<<(N_NODES * IN_FEATS / 4 + 255) / 256, 256>>>(feat);
    // #4: persistent GEMM + fused el/er (profiled slot)
    gemm_hmma_kernel<<<GRID_GEMM, 256, SM_TOTAL>>>(attn_l, attn_r);
    // #5: CSR scan
    scan_kernel<<<1, 1024>>>();
    // #6: CSR fill + CSR-ordered leaky logits
    fill_logits_kernel<<<(N_EDGES + 255) / 256, 256>>>(src, dst);
    // #7: softmax + aggregation
    aggregate_kernel<<<N_NODES, 256>>>(bias, out);
}

// round 9
// speedup vs baseline: 2.2246x; 1.0122x over previous
#include <cuda_runtime.h>
#include <cuda_fp16.h>
#include <math.h>
#include <stdint.h>

// Problem constants
#define N_NODES   10000
#define N_EDGES   160000
#define IN_FEATS  512
#define HEADS     8
#define OUT_FEATS 64
#define HF        (HEADS * OUT_FEATS)   // 512
#define NEG_SLOPE 0.2f

// ---------------- scratch (device globals; no allocs allowed) ----------------
__device__ __half g_hh[N_NODES * HF];        // projected features, fp16
__device__ float g_el[N_NODES * HEADS];
__device__ float g_er[N_NODES * HEADS];
__device__ int   g_cnt[N_NODES + 1];
__device__ int   g_off[N_NODES + 1];
__device__ int   g_cur[N_NODES];
__device__ int   g_srcp[N_EDGES];            // src node per CSR slot
__device__ float g_e[N_EDGES * HEADS];       // leaky logits per CSR slot
__device__ int   g_tile;
__device__ __half g_W16[HF * IN_FEATS];      // W^T fp16: [n][k]
__device__ __half g_Ah16[N_NODES * IN_FEATS]; // feat fp16 hi: [m][k]
__device__ __half g_Al16[N_NODES * IN_FEATS]; // feat fp16 lo: [m][k]

// ------------------------------ PTX helpers ----------------------------------
__device__ __forceinline__ uint32_t smem_u32(const void* p) {
    uint32_t a;
    asm("{ .reg .u64 t; cvta.to.shared.u64 t, %1; cvt.u32.u64 %0, t; }"
        : "=r"(a) : "l"(p));
    return a;
}
__device__ __forceinline__ void cp_async16(uint32_t sa, const void* gp) {
    asm volatile("cp.async.cg.shared.global [%0], [%1], 16;"
                 :: "r"(sa), "l"(gp));
}
__device__ __forceinline__ void cp_async16z(uint32_t sa, const void* gp, int sz) {
    asm volatile("cp.async.cg.shared.global [%0], [%1], 16, %2;"
                 :: "r"(sa), "l"(gp), "r"(sz));
}
__device__ __forceinline__ void cp_commit() {
    asm volatile("cp.async.commit_group;" ::: "memory");
}
template <int N>
__device__ __forceinline__ void cp_wait() {
    asm volatile("cp.async.wait_group %0;" :: "n"(N) : "memory");
}
__device__ __forceinline__ void ldsm4(uint32_t* r, uint32_t addr) {
    asm volatile("ldmatrix.sync.aligned.m8n8.x4.shared.b16 {%0,%1,%2,%3}, [%4];"
                 : "=r"(r[0]), "=r"(r[1]), "=r"(r[2]), "=r"(r[3]) : "r"(addr));
}
__device__ __forceinline__ void mma16816(float* d, const uint32_t* a, const uint32_t* b) {
    asm volatile(
        "mma.sync.aligned.m16n8k16.row.col.f32.f16.f16.f32 "
        "{%0,%1,%2,%3}, {%4,%5,%6,%7}, {%8,%9}, {%0,%1,%2,%3};"
        : "+f"(d[0]), "+f"(d[1]), "+f"(d[2]), "+f"(d[3])
        : "r"(a[0]), "r"(a[1]), "r"(a[2]), "r"(a[3]), "r"(b[0]), "r"(b[1]));
}

// ============== pre-pass 1: W transpose to fp16 + resets ======================
__global__ __launch_bounds__(256) void wsplit_kernel(const float* __restrict__ W)
{
    if (blockIdx.x == 0 && blockIdx.y == 0 && threadIdx.x == 0 && threadIdx.y == 0)
        g_tile = 0;
    {
        int bid = blockIdx.y * 16 + blockIdx.x;
        int gid = bid * 256 + threadIdx.y * 32 + threadIdx.x;
        if (gid <= N_NODES) g_cnt[gid] = 0;
        if (gid < N_NODES)  g_cur[gid] = 0;
    }
    __shared__ float tile[32][33];
    int bx = blockIdx.x;
    int by = blockIdx.y;
    int tx = threadIdx.x;
    for (int i = threadIdx.y; i < 32; i += 8)
        tile[i][tx] = W[(by * 32 + i) * HF + bx * 32 + tx];
    __syncthreads();
    int k = by * 32 + tx;
    for (int i = threadIdx.y; i < 32; i += 8) {
        int n = bx * 32 + i;
        g_W16[n * IN_FEATS + k] = __float2half_rn(tile[tx][i]);
    }
}

// ===== pre-pass 2: feat -> fp16 hi/lo split (+ fused CSR edge count) ==========
__global__ __launch_bounds__(256) void asplit_count_kernel(
    const float* __restrict__ feat, const int* __restrict__ dst)
{
    // fused edge counting on the first 625 blocks
    int eid = blockIdx.x * 256 + threadIdx.x;
    if (eid < N_EDGES) atomicAdd(&g_cnt[dst[eid]], 1);

    int i = blockIdx.x * 256 + threadIdx.x;     // one float4 per thread
    if (i >= N_NODES * IN_FEATS / 4) return;
    float4 v = ((const float4*)feat)[i];
    float f[4] = {v.x, v.y, v.z, v.w};
    __half h[4], lo[4];
    #pragma unroll
    for (int j = 0; j < 4; ++j) {
        h[j]  = __float2half_rn(f[j]);
        lo[j] = __float2half_rn(f[j] - __half2float(h[j]));
    }
    ((uint2*)g_Ah16)[i] = make_uint2(
        ((uint32_t)__half_as_ushort(h[1]) << 16) | __half_as_ushort(h[0]),
        ((uint32_t)__half_as_ushort(h[3]) << 16) | __half_as_ushort(h[2]));
    ((uint2*)g_Al16)[i] = make_uint2(
        ((uint32_t)__half_as_ushort(lo[1]) << 16) | __half_as_ushort(lo[0]),
        ((uint32_t)__half_as_ushort(lo[3]) << 16) | __half_as_ushort(lo[2]));
}

// ============== persistent HMMA fp16x2 GEMM + fused el/er =====================
// Tile 64(M) x 128(N), BK=32. 8 warps: 2(M) x 4(N), warp tile 32x32.
// 3-stage unified cp.async ring; fragment-level pipelining (all ldsm up front).
#define BM 64
#define BN 128
#define BK 32
#define NCH (IN_FEATS / BK)        // 16
#define ROWB 80                    // 64B data + 16B pad
#define AH_OFF 0
#define AL_OFF (BM * ROWB)               // 5120
#define B_OFF  (2 * BM * ROWB)           // 10240
#define STAGE_BYTES (B_OFF + BN * ROWB)  // 20480
#define SM_TOTAL (3 * STAGE_BYTES)       // 61440
#define MT_TILES 157
#define NT_TILES 4
#define NTILES (MT_TILES * NT_TILES)     // 628
#define GRID_GEMM 296

__global__ __launch_bounds__(256, 2) void gemm_hmma_kernel(
    const float* __restrict__ attn_l,
    const float* __restrict__ attn_r)
{
    extern __shared__ char smem[];
    __shared__ int sh_tile;
    uint32_t sb = smem_u32(smem);
    int tid = threadIdx.x;
    int w = tid >> 5;
    int l = tid & 31;
    int wm = (w >> 2) * 32;
    int wn = (w & 3) * 32;
    int lr = l & 15;
    int kc = (l & 16) ? 8 : 0;

    // precomputed ldsm row offsets (tile-invariant)
    uint32_t aoff0 = (uint32_t)(wm + lr) * ROWB;
    uint32_t aoff1 = (uint32_t)(wm + 16 + lr) * ROWB;
    uint32_t boff0 = (uint32_t)(wn + lr) * ROWB;
    uint32_t boff1 = (uint32_t)(wn + 16 + lr) * ROWB;
    // cp.async assignments (tile-invariant)
    int arow = tid >> 2;          // 0..63 (A)
    int ac16 = tid & 3;           // 16B segment within 64B row
    int brow0 = tid >> 1;         // 0..127 (B, 2 x 16B per thread)
    int bseg = (tid & 1) * 2;     // segments {0,1} or {2,3}

    for (;;) {
        if (tid == 0) sh_tile = atomicAdd(&g_tile, 1);
        __syncthreads();
        int t = sh_tile;
        if (t >= NTILES) break;
        int bm = (t >> 2) * BM;
        int bn = (t & 3) * BN;

        float acc[2][4][4];
        #pragma unroll
        for (int a = 0; a < 2; ++a)
            #pragma unroll
            for (int b = 0; b < 4; ++b)
                #pragma unroll
                for (int c = 0; c < 4; ++c) acc[a][b][c] = 0.f;

        int agrow = bm + arow;
        int asz = (agrow < N_NODES) ? 16 : 0;
        if (agrow >= N_NODES) agrow = 0;
        const __half* apH = g_Ah16 + (size_t)agrow * IN_FEATS + ac16 * 8;
        const __half* apL = g_Al16 + (size_t)agrow * IN_FEATS + ac16 * 8;
        const __half* bp0 = g_W16 + (size_t)(bn + brow0) * IN_FEATS + bseg * 8;
        uint32_t sA = (uint32_t)arow * ROWB + ac16 * 16;
        uint32_t sB = (uint32_t)brow0 * ROWB + bseg * 16;

        auto load_chunk = [&](int c) {
            int k0 = c * BK;
            uint32_t st = sb + (c % 3) * STAGE_BYTES;
            cp_async16z(st + AH_OFF + sA, apH + k0, asz);
            cp_async16z(st + AL_OFF + sA, apL + k0, asz);
            cp_async16(st + B_OFF + sB,      bp0 + k0);
            cp_async16(st + B_OFF + sB + 16, bp0 + k0 + 8);
            cp_commit();
        };

        load_chunk(0);
        load_chunk(1);

        for (int c = 0; c < NCH; ++c) {
            if (c < NCH - 1) cp_wait<1>(); else cp_wait<0>();
            __syncthreads();
            if (c + 2 < NCH) load_chunk(c + 2);   // stage (c+2)%3 == (c-1)%3, free

            uint32_t st = sb + (c % 3) * STAGE_BYTES;
            uint32_t sA_h = st + AH_OFF;
            uint32_t sA_l = st + AL_OFF;
            uint32_t sB_h = st + B_OFF;

            // ---- load ALL fragments for both ks up front (12 ldsm burst) ----
            uint32_t bf[2][4][2];        // [ks][fn][2]
            uint32_t ahf[2][2][4];       // [ks][fm][4]
            uint32_t alf[2][2][4];
            #pragma unroll
            for (int ks = 0; ks < 2; ++ks) {
                uint32_t koff = (ks * 16 + kc) * 2;
                uint32_t r[4];
                ldsm4(r, sB_h + boff0 + koff);
                bf[ks][0][0] = r[0]; bf[ks][1][0] = r[1];
                bf[ks][0][1] = r[2]; bf[ks][1][1] = r[3];
                ldsm4(r, sB_h + boff1 + koff);
                bf[ks][2][0] = r[0]; bf[ks][3][0] = r[1];
                bf[ks][2][1] = r[2]; bf[ks][3][1] = r[3];
                ldsm4(ahf[ks][0], sA_h + aoff0 + koff);
                ldsm4(ahf[ks][1], sA_h + aoff1 + koff);
                ldsm4(alf[ks][0], sA_l + aoff0 + koff);
                ldsm4(alf[ks][1], sA_l + aoff1 + koff);
            }
            // ---- dense MMA burst (32 MMAs, no smem dependencies) ----
            #pragma unroll
            for (int ks = 0; ks < 2; ++ks)
                #pragma unroll
                for (int fm = 0; fm < 2; ++fm)
                    #pragma unroll
                    for (int fn = 0; fn < 4; ++fn) {
                        mma16816(acc[fm][fn], ahf[ks][fm], bf[ks][fn]);
                        mma16816(acc[fm][fn], alf[ks][fm], bf[ks][fn]);
                    }
        }

        // ---- epilogue 1: h stores (fp16) ----
        #pragma unroll
        for (int fm = 0; fm < 2; ++fm) {
            int r0 = bm + wm + fm * 16 + (l >> 2);
            int r1 = r0 + 8;
            #pragma unroll
            for (int fn = 0; fn < 4; ++fn) {
                int col = bn + wn + fn * 8 + (l & 3) * 2;
                if (r0 < N_NODES)
                    *(__half2*)(g_hh + (size_t)r0 * HF + col) =
                        __floats2half2_rn(acc[fm][fn][0], acc[fm][fn][1]);
                if (r1 < N_NODES)
                    *(__half2*)(g_hh + (size_t)r1 * HF + col) =
                        __floats2half2_rn(acc[fm][fn][2], acc[fm][fn][3]);
            }
        }

        // ---- epilogue 2: fused el/er (deterministic) ----
        float* pel = (float*)smem;
        float* per = (float*)smem + BM * 4;
        float avl[8], avr[8];
        #pragma unroll
        for (int fn = 0; fn < 4; ++fn) {
            int colg = bn + wn + fn * 8 + (l & 3) * 2;
            avl[2*fn]   = attn_l[colg];
            avl[2*fn+1] = attn_l[colg + 1];
            avr[2*fn]   = attn_r[colg];
            avr[2*fn+1] = attn_r[colg + 1];
        }
        int wnidx = w & 3;
        __syncthreads();   // mainloop smem reads done before reuse
        #pragma unroll
        for (int fm = 0; fm < 2; ++fm) {
            float pl0 = 0.f, pl1 = 0.f, pr0 = 0.f, pr1 = 0.f;
            #pragma unroll
            for (int fn = 0; fn < 4; ++fn) {
                pl0 += acc[fm][fn][0] * avl[2*fn] + acc[fm][fn][1] * avl[2*fn+1];
                pl1 += acc[fm][fn][2] * avl[2*fn] + acc[fm][fn][3] * avl[2*fn+1];
                pr0 += acc[fm][fn][0] * avr[2*fn] + acc[fm][fn][1] * avr[2*fn+1];
                pr1 += acc[fm][fn][2] * avr[2*fn] + acc[fm][fn][3] * avr[2*fn+1];
            }
            #pragma unroll
            for (int o = 1; o <= 2; o <<= 1) {
                pl0 += __shfl_xor_sync(0xFFFFFFFFu, pl0, o);
                pl1 += __shfl_xor_sync(0xFFFFFFFFu, pl1, o);
                pr0 += __shfl_xor_sync(0xFFFFFFFFu, pr0, o);
                pr1 += __shfl_xor_sync(0xFFFFFFFFu, pr1, o);
            }
            if ((l & 3) == 0) {
                int lr0 = wm + fm * 16 + (l >> 2);
                int lr1 = lr0 + 8;
                pel[lr0 * 4 + wnidx] = pl0;
                pel[lr1 * 4 + wnidx] = pl1;
                per[lr0 * 4 + wnidx] = pr0;
                per[lr1 * 4 + wnidx] = pr1;
            }
        }
        __syncthreads();
        if (tid < 2 * BM) {
            int row = tid >> 1;
            int tt = tid & 1;
            int grow = bm + row;
            if (grow < N_NODES) {
                float el = pel[row * 4 + 2 * tt] + pel[row * 4 + 2 * tt + 1];
                float er = per[row * 4 + 2 * tt] + per[row * 4 + 2 * tt + 1];
                int hd = (t & 3) * 2 + tt;
                g_el[grow * HEADS + hd] = el;
                g_er[grow * HEADS + hd] = er;
            }
        }
        __syncthreads();   // protect pel/per before next tile's prologue
    }
}

// ------------------------------ CSR scan --------------------------------------
#define SCAN_CHUNK 10
__global__ __launch_bounds__(1024) void scan_kernel()
{
    __shared__ int sh[1024];
    int t = threadIdx.x;
    int base = t * SCAN_CHUNK;
    int vloc[SCAN_CHUNK];
    int s = 0;
    #pragma unroll
    for (int j = 0; j < SCAN_CHUNK; j++) {
        int idx = base + j;
        int c = (idx < N_NODES) ? g_cnt[idx] : 0;
        vloc[j] = c;
        s += c;
    }
    sh[t] = s;
    __syncthreads();
    for (int d = 1; d < 1024; d <<= 1) {
        int add = (t >= d) ? sh[t - d] : 0;
        __syncthreads();
        sh[t] += add;
        __syncthreads();
    }
    int run = sh[t] - s;
    #pragma unroll
    for (int j = 0; j < SCAN_CHUNK; j++) {
        int idx = base + j;
        if (idx <= N_NODES) g_off[idx] = run;
        run += vloc[j];
    }
}

// -------- fill CSR slots + precompute CSR-ordered leaky logits ----------------
__global__ __launch_bounds__(256) void fill_logits_kernel(
    const int* __restrict__ src, const int* __restrict__ dst)
{
    int e = blockIdx.x * blockDim.x + threadIdx.x;
    if (e >= N_EDGES) return;
    int d = dst[e];
    int s = src[e];
    int pos = atomicAdd(&g_cur[d], 1);
    int i = g_off[d] + pos;
    g_srcp[i] = s;
    float4 l0 = *(const float4*)&g_el[s * HEADS];
    float4 l1 = *(const float4*)&g_el[s * HEADS + 4];
    float4 r0 = *(const float4*)&g_er[d * HEADS];
    float4 r1 = *(const float4*)&g_er[d * HEADS + 4];
    float v[8] = {l0.x + r0.x, l0.y + r0.y, l0.z + r0.z, l0.w + r0.w,
                  l1.x + r1.x, l1.y + r1.y, l1.z + r1.z, l1.w + r1.w};
    #pragma unroll
    for (int h = 0; h < 8; ++h)
        v[h] = (v[h] > 0.f) ? v[h] : NEG_SLOPE * v[h];
    *(float4*)&g_e[i * HEADS]     = make_float4(v[0], v[1], v[2], v[3]);
    *(float4*)&g_e[i * HEADS + 4] = make_float4(v[4], v[5], v[6], v[7]);
}

// ---------- softmax over incoming edges + weighted aggregation ---------------
__global__ __launch_bounds__(256) void aggregate_kernel(
    const float* __restrict__ bias,
    float* __restrict__ out)
{
    __shared__ float2 buf[8][32];
    int n = blockIdx.x;
    int hd = threadIdx.x >> 5;
    int lane = threadIdx.x & 31;

    int beg = g_off[n];
    int end = g_off[n + 1];

    float m = -INFINITY;
    for (int i = beg + lane; i < end; i += 32)
        m = fmaxf(m, g_e[i * HEADS + hd]);
    #pragma unroll
    for (int o = 16; o > 0; o >>= 1)
        m = fmaxf(m, __shfl_xor_sync(0xFFFFFFFFu, m, o));

    float ssum = 0.f;
    float acc0 = 0.f, acc1 = 0.f;
    for (int base = beg; base < end; base += 32) {
        int cnt = end - base; if (cnt > 32) cnt = 32;
        if (lane < cnt) {
            int i = base + lane;
            float p = __expf(g_e[i * HEADS + hd] - m);
            ssum += p;
            buf[hd][lane] = make_float2(p, __int_as_float(g_srcp[i]));
        }
        __syncwarp();
        if (cnt == 32) {
            #pragma unroll 8
            for (int j = 0; j < 32; ++j) {
                float2 ps = buf[hd][j];
                int s = __float_as_int(ps.y);
                __half2 hv = *(const __half2*)(g_hh + (size_t)s * HF + hd * OUT_FEATS + 2 * lane);
                float2 f = __half22float2(hv);
                acc0 = fmaf(ps.x, f.x, acc0);
                acc1 = fmaf(ps.x, f.y, acc1);
            }
        } else {
            for (int j = 0; j < cnt; ++j) {
                float2 ps = buf[hd][j];
                int s = __float_as_int(ps.y);
                __half2 hv = *(const __half2*)(g_hh + (size_t)s * HF + hd * OUT_FEATS + 2 * lane);
                float2 f = __half22float2(hv);
                acc0 = fmaf(ps.x, f.x, acc0);
                acc1 = fmaf(ps.x, f.y, acc1);
            }
        }
        __syncwarp();
    }
    #pragma unroll
    for (int o = 16; o > 0; o >>= 1)
        ssum += __shfl_xor_sync(0xFFFFFFFFu, ssum, o);

    float inv = (ssum > 0.f) ? (1.0f / ssum) : 0.f;

    int ob = n * HF + hd * OUT_FEATS + 2 * lane;
    float b0 = bias[hd * OUT_FEATS + 2 * lane];
    float b1 = bias[hd * OUT_FEATS + 2 * lane + 1];
    *(float2*)(out + ob) = make_float2(acc0 * inv + b0, acc1 * inv + b1);
}

// ------------------------------- launcher ------------------------------------
extern "C" void kernel_launch(void* const* d_in, const int* in_sizes, int n_in,
                              void* d_out, int out_size)
{
    const float* feat   = (const float*)d_in[0];
    const float* W      = (const float*)d_in[1];
    const float* attn_l = (const float*)d_in[2];
    const float* attn_r = (const float*)d_in[3];
    const float* bias   = (const float*)d_in[4];
    const int*   src    = (const int*)d_in[5];
    const int*   dst    = (const int*)d_in[6];
    float* out = (float*)d_out;

    cudaFuncSetAttribute(gemm_hmma_kernel,
                         cudaFuncAttributeMaxDynamicSharedMemorySize, SM_TOTAL);

    // #1: W fp16 transpose (+ reset ticket + zero CSR counters)
    wsplit_kernel<<<dim3(16, 16), dim3(32, 8)>>>(W);
    // #2: feat fp16 hi/lo split + fused CSR edge count
    asplit_count_kernel<<<(N_NODES * IN_FEATS / 4 + 255) / 256, 256>>>(feat, dst);
    // #3: CSR scan
    scan_kernel<<<1, 1024>>>();
    // #4: persistent GEMM + fused el/er (profiled slot)
    gemm_hmma_kernel<<<GRID_GEMM, 256, SM_TOTAL>>>(attn_l, attn_r);
    // #5: CSR fill + CSR-ordered leaky logits
    fill_logits_kernel<<<(N_EDGES + 255) / 256, 256>>>(src, dst);
    // #6: softmax + aggregation
    aggregate_kernel<<<N_NODES, 256>>>(bias, out);
}